// round 10
// baseline (speedup 1.0000x reference)
#include <cuda_runtime.h>
#include <cuda_fp16.h>
#include <math.h>
#include <stdint.h>

// ---------------- Problem constants ----------------
#define NN    30000
#define EE    480000
#define ETOT  (EE + NN)
#define FIN   4096
#define D1    512
#define H1    4
#define C1    128
#define CLS   6
#define SLOPE 0.2f
#define NEGBIG (-3.402823466e38f)

// ---------------- Device scratch ----------------
__device__ __half g_h1h[(size_t)NN * D1];   // layer-1 linear output, fp16
__device__ float g_out1[(size_t)NN * D1];   // post-attention + ELU (fp32)
__device__ float g_asrc1[NN * H1];
__device__ float g_adst1[NN * H1];
__device__ float g_h2[NN * CLS];
__device__ float g_as2[NN];
__device__ float g_ad2[NN];
__device__ int   g_deg[NN];
__device__ int   g_off[NN + 1];
__device__ int   g_cur[NN];
__device__ int   g_srcs[ETOT];

// fp16 W1 transposed: [N=512][K=4096]
__device__ __half g_w1t[(size_t)D1 * FIN];

__device__ __forceinline__ float lrelu(float v) { return v > 0.0f ? v : SLOPE * v; }

// ==================== helpers ====================
__device__ __forceinline__ uint32_t smem_u32(const void* p) {
    uint32_t a;
    asm("{ .reg .u64 t; cvta.to.shared.u64 t, %1; cvt.u32.u64 %0, t; }" : "=r"(a) : "l"(p));
    return a;
}

__device__ __forceinline__ void cpa16(uint32_t dst, const void* src) {
    asm volatile("cp.async.cg.shared.global [%0], [%1], 16;\n"
                 :: "r"(dst), "l"(src) : "memory");
}

__device__ __forceinline__ void ldm_x4(uint32_t addr, uint32_t& r0, uint32_t& r1,
                                       uint32_t& r2, uint32_t& r3) {
    asm volatile("ldmatrix.sync.aligned.m8n8.x4.shared.b16 {%0,%1,%2,%3}, [%4];"
                 : "=r"(r0), "=r"(r1), "=r"(r2), "=r"(r3) : "r"(addr));
}

__device__ __forceinline__ void mma_f16(float& d0, float& d1, float& d2, float& d3,
                                        uint32_t a0, uint32_t a1, uint32_t a2, uint32_t a3,
                                        uint32_t b0, uint32_t b1) {
    asm volatile("mma.sync.aligned.m16n8k16.row.col.f32.f16.f16.f32 "
                 "{%0,%1,%2,%3}, {%4,%5,%6,%7}, {%8,%9}, {%0,%1,%2,%3};"
                 : "+f"(d0), "+f"(d1), "+f"(d2), "+f"(d3)
                 : "r"(a0), "r"(a1), "r"(a2), "r"(a3), "r"(b0), "r"(b1));
}

__device__ __forceinline__ uint32_t pack_h2(float a, float b) {
    __half2 h = __halves2half2(__float2half_rn(a), __float2half_rn(b));
    return *(uint32_t*)&h;
}

// ==================== W1 -> fp16 transposed (32x32 tile) ====================
__global__ __launch_bounds__(256) void convw1_kernel(const float* __restrict__ W1) {
    __shared__ float tile[32][33];
    const int kb = blockIdx.y * 32;
    const int nb = blockIdx.x * 32;
    const int t = threadIdx.x;
    const int r = t >> 5, c = t & 31;
#pragma unroll
    for (int rr = r; rr < 32; rr += 8)
        tile[rr][c] = W1[(size_t)(kb + rr) * D1 + nb + c];
    __syncthreads();
#pragma unroll
    for (int rr = r; rr < 32; rr += 8) {
        float v = tile[c][rr];
        g_w1t[(size_t)(nb + rr) * FIN + kb + c] = __float2half_rn(v);
    }
}

// ==================== GEMM1: fused-convert fp16 mma.sync, 128x256 tile ====================
#define BK       32
#define CHUNKS   (FIN / BK)      // 128
#define TILE_A_B (128 * 80)      // 10240
#define TILE_B_B (256 * 80)      // 20480
#define OFF_A    0
#define OFF_B    (TILE_A_B)
#define STAGE_B  (TILE_A_B + TILE_B_B)   // 30720
#define SMEM_SZ  (2 * STAGE_B)           // 61440

__global__ __launch_bounds__(256) void mma1_kernel(const float* __restrict__ x) {
    extern __shared__ __align__(16) char dsm[];
    const uint32_t sb = smem_u32(dsm);

    const int tid = threadIdx.x;
    const int wid = tid >> 5;
    const int lane = tid & 31;
    const int warp_m = wid >> 2;    // 0..1
    const int warp_n = wid & 3;     // 0..3
    const int block_row = blockIdx.y * 128;
    const int nbase = blockIdx.x * 256;

    const int a_r = tid >> 1;
    const int a_half = tid & 1;
    const bool a_ok = (block_row + a_r) < NN;
    const float* a_src = x + (size_t)(block_row + a_r) * FIN + a_half * 16;
    const uint32_t a_dso = (uint32_t)(a_r * 80 + a_half * 32);

    float4 xr[4];
    auto ldA = [&](int c) {
        if (a_ok) {
            const float4* p = (const float4*)(a_src + c * BK);
#pragma unroll
            for (int q = 0; q < 4; q++) xr[q] = p[q];
        } else {
            float4 z = make_float4(0.f, 0.f, 0.f, 0.f);
#pragma unroll
            for (int q = 0; q < 4; q++) xr[q] = z;
        }
    };
    auto stsA = [&](int s) {
        const uint32_t base = sb + s * STAGE_B;
        uint4 h0, h1;
        h0.x = pack_h2(xr[0].x, xr[0].y); h0.y = pack_h2(xr[0].z, xr[0].w);
        h0.z = pack_h2(xr[1].x, xr[1].y); h0.w = pack_h2(xr[1].z, xr[1].w);
        h1.x = pack_h2(xr[2].x, xr[2].y); h1.y = pack_h2(xr[2].z, xr[2].w);
        h1.z = pack_h2(xr[3].x, xr[3].y); h1.w = pack_h2(xr[3].z, xr[3].w);
        uint32_t ah = base + OFF_A + a_dso;
        asm volatile("st.shared.v4.b32 [%0], {%1,%2,%3,%4};" :: "r"(ah), "r"(h0.x), "r"(h0.y), "r"(h0.z), "r"(h0.w));
        asm volatile("st.shared.v4.b32 [%0], {%1,%2,%3,%4};" :: "r"(ah + 16), "r"(h1.x), "r"(h1.y), "r"(h1.z), "r"(h1.w));
    };

    auto cpB = [&](int c, int s) {
        const uint32_t base = sb + s * STAGE_B;
        const int kbase = c * BK;
#pragma unroll
        for (int i = tid; i < 1024; i += 256) {
            int r = i >> 2, q = i & 3;
            uint32_t dso = (uint32_t)(r * 80 + q * 16);
            size_t se = (size_t)(nbase + r) * FIN + kbase + q * 8;
            cpa16(base + OFF_B + dso, g_w1t + se);
        }
    };

    const uint32_t a_off = (uint32_t)((warp_m * 64 + (lane & 15)) * 80 + (lane >> 4) * 16);
    const uint32_t b_off = (uint32_t)((warp_n * 64 + (lane & 7) + ((lane >> 4) << 3)) * 80 +
                                      ((lane >> 3) & 1) * 16);

    float acc[4][8][4];
#pragma unroll
    for (int i = 0; i < 4; i++)
#pragma unroll
        for (int j = 0; j < 8; j++)
#pragma unroll
            for (int q = 0; q < 4; q++) acc[i][j][q] = 0.0f;

    ldA(0);
    stsA(0);
    cpB(0, 0);
    asm volatile("cp.async.commit_group;\n" ::: "memory");
    ldA(1);

    for (int c = 0; c < CHUNKS; c++) {
        const int s = c & 1;
        asm volatile("cp.async.wait_group 0;\n" ::: "memory");
        __syncthreads();

        if (c + 1 < CHUNKS) {
            stsA(s ^ 1);
            cpB(c + 1, s ^ 1);
            asm volatile("cp.async.commit_group;\n" ::: "memory");
        }
        if (c + 2 < CHUNKS) ldA(c + 2);

        const uint32_t stg = sb + s * STAGE_B;
        const uint32_t a_base = stg + OFF_A + a_off;
        const uint32_t b_base = stg + OFF_B + b_off;

#pragma unroll
        for (int kk = 0; kk < 2; kk++) {
            uint32_t av[4][4];
#pragma unroll
            for (int i = 0; i < 4; i++) {
                uint32_t ao = (uint32_t)(i * 16 * 80 + kk * 32);
                ldm_x4(a_base + ao, av[i][0], av[i][1], av[i][2], av[i][3]);
            }
#pragma unroll
            for (int j2 = 0; j2 < 4; j2++) {
                uint32_t b0, b1, b2, b3;
                uint32_t bo = (uint32_t)(j2 * 16 * 80 + kk * 32);
                ldm_x4(b_base + bo, b0, b1, b2, b3);
#pragma unroll
                for (int i = 0; i < 4; i++) {
                    float* d0 = acc[i][2 * j2];
                    float* d1 = acc[i][2 * j2 + 1];
                    mma_f16(d0[0], d0[1], d0[2], d0[3],
                            av[i][0], av[i][1], av[i][2], av[i][3], b0, b1);
                    mma_f16(d1[0], d1[1], d1[2], d1[3],
                            av[i][0], av[i][1], av[i][2], av[i][3], b2, b3);
                }
            }
        }
    }

    // epilogue: write fp16 h1
#pragma unroll
    for (int i = 0; i < 4; i++) {
        int row0 = block_row + warp_m * 64 + i * 16 + (lane >> 2);
#pragma unroll
        for (int j = 0; j < 8; j++) {
            int col = nbase + warp_n * 64 + j * 8 + (lane & 3) * 2;
            if (row0 < NN)
                *(uint32_t*)(g_h1h + (size_t)row0 * D1 + col) = pack_h2(acc[i][j][0], acc[i][j][1]);
            if (row0 + 8 < NN)
                *(uint32_t*)(g_h1h + (size_t)(row0 + 8) * D1 + col) = pack_h2(acc[i][j][2], acc[i][j][3]);
        }
    }
}

// ==================== CSR build ====================
__global__ void zero_deg_kernel() {
    int i = blockIdx.x * blockDim.x + threadIdx.x;
    if (i < NN) g_deg[i] = 0;
}

__global__ void count_kernel(const int* __restrict__ ei) {
    int e = blockIdx.x * blockDim.x + threadIdx.x;
    if (e >= ETOT) return;
    int dst = (e < EE) ? ei[EE + e] : (e - EE);
    atomicAdd(&g_deg[dst], 1);
}

__global__ __launch_bounds__(1024) void scan_kernel() {
    __shared__ int part[1024];
    const int t = threadIdx.x;
    const int CH = (NN + 1023) / 1024;
    const int base = t * CH;
    int s = 0;
    for (int i = 0; i < CH; i++) {
        int idx = base + i;
        if (idx < NN) s += g_deg[idx];
    }
    part[t] = s;
    __syncthreads();
    for (int o = 1; o < 1024; o <<= 1) {
        int v = (t >= o) ? part[t - o] : 0;
        __syncthreads();
        part[t] += v;
        __syncthreads();
    }
    int run = part[t] - s;
    for (int i = 0; i < CH; i++) {
        int idx = base + i;
        if (idx < NN) {
            g_off[idx] = run;
            g_cur[idx] = run;
            run += g_deg[idx];
        }
    }
    if (t == 1023) g_off[NN] = part[1023];
}

__global__ void scatter_kernel(const int* __restrict__ ei) {
    int e = blockIdx.x * blockDim.x + threadIdx.x;
    if (e >= ETOT) return;
    int src, dst;
    if (e < EE) { src = ei[e]; dst = ei[EE + e]; }
    else        { src = e - EE; dst = e - EE; }
    int pos = atomicAdd(&g_cur[dst], 1);
    g_srcs[pos] = src;
}

// ==================== Layer 1 alphas (fp16 h1) ====================
__global__ void alpha1_kernel(const float* __restrict__ a_s, const float* __restrict__ a_d) {
    int warp = blockIdx.x * 8 + (threadIdx.x >> 5);
    int lane = threadIdx.x & 31;
    if (warp >= NN) return;
    const __half2* row2 = (const __half2*)(g_h1h + (size_t)warp * D1);
#pragma unroll
    for (int h = 0; h < H1; h++) {
        float ss = 0.f, sd = 0.f;
#pragma unroll
        for (int k = 0; k < 2; k++) {
            int p = h * 64 + lane + 32 * k;
            float2 v = __half22float2(row2[p]);
            int c = 2 * p;
            ss = fmaf(v.x, a_s[c], ss);     ss = fmaf(v.y, a_s[c + 1], ss);
            sd = fmaf(v.x, a_d[c], sd);     sd = fmaf(v.y, a_d[c + 1], sd);
        }
#pragma unroll
        for (int o = 16; o; o >>= 1) {
            ss += __shfl_xor_sync(0xffffffffu, ss, o);
            sd += __shfl_xor_sync(0xffffffffu, sd, o);
        }
        if (lane == 0) {
            g_asrc1[warp * H1 + h] = ss;
            g_adst1[warp * H1 + h] = sd;
        }
    }
}

// ==================== Layer 1 softmax (online) + aggregate + ELU ====================
__global__ __launch_bounds__(128) void agg1_kernel(const float* __restrict__ b1) {
    const int n = blockIdx.x;
    const int t = threadIdx.x;
    const int h = t >> 5;
    const int lane = t & 31;
    const int s0 = g_off[n];
    const int deg = g_off[n + 1] - s0;

    __shared__ float adsts[H1];
    __shared__ float sm[H1];
    __shared__ float sinv[H1];
    __shared__ float wm[4][H1];
    __shared__ float ws[4][H1];
    __shared__ int   ssrc[128];
    __shared__ float scoef[128 * H1];

    if (t < H1) adsts[t] = g_adst1[n * H1 + t];
    __syncthreads();

    const float4* asrc4 = (const float4*)g_asrc1;

    // online (max, sum) pass
    float m[H1] = {NEGBIG, NEGBIG, NEGBIG, NEGBIG};
    float sacc[H1] = {0.f, 0.f, 0.f, 0.f};
    for (int i = t; i < deg; i += 128) {
        float4 as = asrc4[g_srcs[s0 + i]];
        float l[H1];
        l[0] = lrelu(as.x + adsts[0]);
        l[1] = lrelu(as.y + adsts[1]);
        l[2] = lrelu(as.z + adsts[2]);
        l[3] = lrelu(as.w + adsts[3]);
#pragma unroll
        for (int hh = 0; hh < H1; hh++) {
            float M = fmaxf(m[hh], l[hh]);
            sacc[hh] = sacc[hh] * expf(m[hh] - M) + expf(l[hh] - M);
            m[hh] = M;
        }
    }
#pragma unroll
    for (int o = 16; o; o >>= 1) {
#pragma unroll
        for (int hh = 0; hh < H1; hh++) {
            float mo = __shfl_xor_sync(0xffffffffu, m[hh], o);
            float so = __shfl_xor_sync(0xffffffffu, sacc[hh], o);
            float M = fmaxf(m[hh], mo);
            sacc[hh] = sacc[hh] * expf(m[hh] - M) + so * expf(mo - M);
            m[hh] = M;
        }
    }
    if (lane == 0) {
#pragma unroll
        for (int hh = 0; hh < H1; hh++) { wm[h][hh] = m[hh]; ws[h][hh] = sacc[hh]; }
    }
    __syncthreads();
    if (t < H1) {
        float M = wm[0][t], S = ws[0][t];
#pragma unroll
        for (int w = 1; w < 4; w++) {
            float mo = wm[w][t], so = ws[w][t];
            float M2 = fmaxf(M, mo);
            S = S * expf(M - M2) + so * expf(mo - M2);
            M = M2;
        }
        sm[t] = M;
        sinv[t] = 1.0f / S;
    }
    __syncthreads();

    // aggregation: thread t owns channels [4t, 4t+4)
    float ax = 0.f, ay = 0.f, az = 0.f, aw = 0.f;
    for (int base = 0; base < deg; base += 128) {
        int cnt = min(128, deg - base);
        if (t < cnt) {
            int s = g_srcs[s0 + base + t];
            ssrc[t] = s;
            float4 as = asrc4[s];
            scoef[t * H1 + 0] = expf(lrelu(as.x + adsts[0]) - sm[0]) * sinv[0];
            scoef[t * H1 + 1] = expf(lrelu(as.y + adsts[1]) - sm[1]) * sinv[1];
            scoef[t * H1 + 2] = expf(lrelu(as.z + adsts[2]) - sm[2]) * sinv[2];
            scoef[t * H1 + 3] = expf(lrelu(as.w + adsts[3]) - sm[3]) * sinv[3];
        }
        __syncthreads();
        int i = 0;
        for (; i + 2 <= cnt; i += 2) {
            int sA = ssrc[i], sB = ssrc[i + 1];
            uint2 uA = *(const uint2*)(g_h1h + (size_t)sA * D1 + 4 * t);
            uint2 uB = *(const uint2*)(g_h1h + (size_t)sB * D1 + 4 * t);
            float2 a0 = __half22float2(*(__half2*)&uA.x);
            float2 a1 = __half22float2(*(__half2*)&uA.y);
            float2 b0 = __half22float2(*(__half2*)&uB.x);
            float2 b1 = __half22float2(*(__half2*)&uB.y);
            float cA = scoef[i * H1 + h];
            float cB = scoef[(i + 1) * H1 + h];
            ax = fmaf(cA, a0.x, ax); ay = fmaf(cA, a0.y, ay);
            az = fmaf(cA, a1.x, az); aw = fmaf(cA, a1.y, aw);
            ax = fmaf(cB, b0.x, ax); ay = fmaf(cB, b0.y, ay);
            az = fmaf(cB, b1.x, az); aw = fmaf(cB, b1.y, aw);
        }
        if (i < cnt) {
            uint2 u = *(const uint2*)(g_h1h + (size_t)ssrc[i] * D1 + 4 * t);
            float2 v0 = __half22float2(*(__half2*)&u.x);
            float2 v1 = __half22float2(*(__half2*)&u.y);
            float cf = scoef[i * H1 + h];
            ax = fmaf(cf, v0.x, ax); ay = fmaf(cf, v0.y, ay);
            az = fmaf(cf, v1.x, az); aw = fmaf(cf, v1.y, aw);
        }
        __syncthreads();
    }

    float4 bb = *(const float4*)(b1 + 4 * t);
    float4 o;
    o.x = ax + bb.x; o.x = o.x > 0.f ? o.x : expm1f(o.x);
    o.y = ay + bb.y; o.y = o.y > 0.f ? o.y : expm1f(o.y);
    o.z = az + bb.z; o.z = o.z > 0.f ? o.z : expm1f(o.z);
    o.w = aw + bb.w; o.w = o.w > 0.f ? o.w : expm1f(o.w);
    *(float4*)(g_out1 + (size_t)n * D1 + 4 * t) = o;
}

// ==================== Layer 2: gemm2 + fused alpha2 ====================
__global__ __launch_bounds__(256) void gemm2_kernel(const float* __restrict__ W2,
                                                    const float* __restrict__ a_s,
                                                    const float* __restrict__ a_d) {
    __shared__ float w[D1 * CLS];
    int t = threadIdx.x;
    for (int i = t; i < D1 * CLS; i += 256) w[i] = W2[i];
    __syncthreads();
    int warp = blockIdx.x * 8 + (t >> 5);
    int lane = t & 31;
    if (warp >= NN) return;
    const float* row = g_out1 + (size_t)warp * D1;
    float acc[CLS] = {0.f, 0.f, 0.f, 0.f, 0.f, 0.f};
    for (int k = lane; k < D1; k += 32) {
        float v = row[k];
        const float* wr = &w[k * CLS];
#pragma unroll
        for (int c = 0; c < CLS; c++) acc[c] = fmaf(v, wr[c], acc[c]);
    }
#pragma unroll
    for (int o = 16; o; o >>= 1)
#pragma unroll
        for (int c = 0; c < CLS; c++) acc[c] += __shfl_xor_sync(0xffffffffu, acc[c], o);
    if (lane == 0) {
        float s2 = 0.f, d2 = 0.f;
#pragma unroll
        for (int c = 0; c < CLS; c++) {
            g_h2[warp * CLS + c] = acc[c];
            s2 = fmaf(acc[c], a_s[c], s2);
            d2 = fmaf(acc[c], a_d[c], d2);
        }
        g_as2[warp] = s2;
        g_ad2[warp] = d2;
    }
}

// ==================== Layer 2 aggregation ====================
__global__ __launch_bounds__(128) void agg2_kernel(const float* __restrict__ b2,
                                                   float* __restrict__ out) {
    int n = blockIdx.x * 4 + (threadIdx.x >> 5);
    int lane = threadIdx.x & 31;
    if (n >= NN) return;
    int s0 = g_off[n];
    int deg = g_off[n + 1] - s0;
    float ad = g_ad2[n];

    float lmax = -INFINITY;
    for (int i = lane; i < deg; i += 32) {
        int s = g_srcs[s0 + i];
        lmax = fmaxf(lmax, lrelu(g_as2[s] + ad));
    }
#pragma unroll
    for (int o = 16; o; o >>= 1) lmax = fmaxf(lmax, __shfl_xor_sync(0xffffffffu, lmax, o));

    float lsum = 0.f;
    for (int i = lane; i < deg; i += 32) {
        int s = g_srcs[s0 + i];
        lsum += expf(lrelu(g_as2[s] + ad) - lmax);
    }
#pragma unroll
    for (int o = 16; o; o >>= 1) lsum += __shfl_xor_sync(0xffffffffu, lsum, o);
    float inv = 1.0f / lsum;

    float acc[CLS] = {0.f, 0.f, 0.f, 0.f, 0.f, 0.f};
    for (int i = lane; i < deg; i += 32) {
        int s = g_srcs[s0 + i];
        float coef = expf(lrelu(g_as2[s] + ad) - lmax) * inv;
        const float* hp = g_h2 + s * CLS;
#pragma unroll
        for (int c = 0; c < CLS; c++) acc[c] = fmaf(coef, hp[c], acc[c]);
    }
#pragma unroll
    for (int o = 16; o; o >>= 1)
#pragma unroll
        for (int c = 0; c < CLS; c++) acc[c] += __shfl_xor_sync(0xffffffffu, acc[c], o);

    if (lane == 0) {
#pragma unroll
        for (int c = 0; c < CLS; c++) out[n * CLS + c] = acc[c] + b2[c];
    }
}

// ==================== Launch ====================
extern "C" void kernel_launch(void* const* d_in, const int* in_sizes, int n_in,
                              void* d_out, int out_size) {
    const float* x   = (const float*)d_in[0];
    const int*   ei  = (const int*)  d_in[1];
    const float* W1  = (const float*)d_in[2];
    const float* as1 = (const float*)d_in[3];
    const float* ad1 = (const float*)d_in[4];
    const float* b1  = (const float*)d_in[5];
    const float* W2  = (const float*)d_in[6];
    const float* as2 = (const float*)d_in[7];
    const float* ad2 = (const float*)d_in[8];
    const float* b2  = (const float*)d_in[9];
    float* out = (float*)d_out;

    static bool attr_set = false;
    if (!attr_set) {
        cudaFuncSetAttribute(mma1_kernel, cudaFuncAttributeMaxDynamicSharedMemorySize, SMEM_SZ);
        attr_set = true;
    }

    // CSR build
    zero_deg_kernel<<<(NN + 255) / 256, 256>>>();
    count_kernel<<<(ETOT + 255) / 256, 256>>>(ei);
    scan_kernel<<<1, 1024>>>();
    scatter_kernel<<<(ETOT + 255) / 256, 256>>>(ei);

    // W1 -> fp16 transposed
    convw1_kernel<<<dim3(D1 / 32, FIN / 32), 256>>>(W1);

    // Layer 1
    mma1_kernel<<<dim3(D1 / 256, (NN + 127) / 128), 256, SMEM_SZ>>>(x);
    alpha1_kernel<<<(NN + 7) / 8, 256>>>(as1, ad1);
    agg1_kernel<<<NN, 128>>>(b1);

    // Layer 2 (gemm2 + alpha2 fused), then aggregation
    gemm2_kernel<<<(NN + 7) / 8, 256>>>(W2, as2, ad2);
    agg2_kernel<<<(NN + 3) / 4, 128>>>(b2, out);
}

// round 11
// speedup vs baseline: 1.0948x; 1.0948x over previous
#include <cuda_runtime.h>
#include <cuda_fp16.h>
#include <math.h>
#include <stdint.h>

// ---------------- Problem constants ----------------
#define NN    30000
#define EE    480000
#define ETOT  (EE + NN)
#define FIN   4096
#define D1    512
#define H1    4
#define C1    128
#define CLS   6
#define SLOPE 0.2f

// ---------------- Device scratch ----------------
__device__ __half g_h1h[(size_t)NN * D1];   // layer-1 linear output, fp16
__device__ float g_out1[(size_t)NN * D1];   // post-attention + ELU (fp32)
__device__ float g_asrc1[NN * H1];
__device__ float g_adst1[NN * H1];
__device__ float g_h2[NN * CLS];
__device__ float g_as2[NN];
__device__ float g_ad2[NN];
__device__ int   g_deg[NN];
__device__ int   g_off[NN + 1];
__device__ int   g_cur[NN];
__device__ int   g_srcs[ETOT];

// fp16 W1 transposed: [N=512][K=4096]
__device__ __half g_w1t[(size_t)D1 * FIN];

__device__ __forceinline__ float lrelu(float v) { return v > 0.0f ? v : SLOPE * v; }

// ==================== helpers ====================
__device__ __forceinline__ uint32_t smem_u32(const void* p) {
    uint32_t a;
    asm("{ .reg .u64 t; cvta.to.shared.u64 t, %1; cvt.u32.u64 %0, t; }" : "=r"(a) : "l"(p));
    return a;
}

__device__ __forceinline__ void cpa16(uint32_t dst, const void* src) {
    asm volatile("cp.async.cg.shared.global [%0], [%1], 16;\n"
                 :: "r"(dst), "l"(src) : "memory");
}

__device__ __forceinline__ void ldm_x4(uint32_t addr, uint32_t& r0, uint32_t& r1,
                                       uint32_t& r2, uint32_t& r3) {
    asm volatile("ldmatrix.sync.aligned.m8n8.x4.shared.b16 {%0,%1,%2,%3}, [%4];"
                 : "=r"(r0), "=r"(r1), "=r"(r2), "=r"(r3) : "r"(addr));
}

__device__ __forceinline__ void mma_f16(float& d0, float& d1, float& d2, float& d3,
                                        uint32_t a0, uint32_t a1, uint32_t a2, uint32_t a3,
                                        uint32_t b0, uint32_t b1) {
    asm volatile("mma.sync.aligned.m16n8k16.row.col.f32.f16.f16.f32 "
                 "{%0,%1,%2,%3}, {%4,%5,%6,%7}, {%8,%9}, {%0,%1,%2,%3};"
                 : "+f"(d0), "+f"(d1), "+f"(d2), "+f"(d3)
                 : "r"(a0), "r"(a1), "r"(a2), "r"(a3), "r"(b0), "r"(b1));
}

__device__ __forceinline__ uint32_t pack_h2(float a, float b) {
    __half2 h = __halves2half2(__float2half_rn(a), __float2half_rn(b));
    return *(uint32_t*)&h;
}

// ==================== W1 -> fp16 transposed (32x32 tile) ====================
__global__ __launch_bounds__(256) void convw1_kernel(const float* __restrict__ W1) {
    __shared__ float tile[32][33];
    const int kb = blockIdx.y * 32;
    const int nb = blockIdx.x * 32;
    const int t = threadIdx.x;
    const int r = t >> 5, c = t & 31;
#pragma unroll
    for (int rr = r; rr < 32; rr += 8)
        tile[rr][c] = W1[(size_t)(kb + rr) * D1 + nb + c];
    __syncthreads();
#pragma unroll
    for (int rr = r; rr < 32; rr += 8) {
        float v = tile[c][rr];
        g_w1t[(size_t)(nb + rr) * FIN + kb + c] = __float2half_rn(v);
    }
}

// ==================== GEMM1: fused-convert fp16 mma.sync, 128x256 tile ====================
#define BK       32
#define CHUNKS   (FIN / BK)      // 128
#define TILE_A_B (128 * 80)      // 10240
#define TILE_B_B (256 * 80)      // 20480
#define OFF_A    0
#define OFF_B    (TILE_A_B)
#define STAGE_B  (TILE_A_B + TILE_B_B)   // 30720
#define SMEM_SZ  (2 * STAGE_B)           // 61440

__global__ __launch_bounds__(256) void mma1_kernel(const float* __restrict__ x) {
    extern __shared__ __align__(16) char dsm[];
    const uint32_t sb = smem_u32(dsm);

    const int tid = threadIdx.x;
    const int wid = tid >> 5;
    const int lane = tid & 31;
    const int warp_m = wid >> 2;    // 0..1
    const int warp_n = wid & 3;     // 0..3
    const int block_row = blockIdx.y * 128;
    const int nbase = blockIdx.x * 256;

    const int a_r = tid >> 1;
    const int a_half = tid & 1;
    const bool a_ok = (block_row + a_r) < NN;
    const float* a_src = x + (size_t)(block_row + a_r) * FIN + a_half * 16;
    const uint32_t a_dso = (uint32_t)(a_r * 80 + a_half * 32);

    float4 xr[4];
    auto ldA = [&](int c) {
        if (a_ok) {
            const float4* p = (const float4*)(a_src + c * BK);
#pragma unroll
            for (int q = 0; q < 4; q++) xr[q] = p[q];
        } else {
            float4 z = make_float4(0.f, 0.f, 0.f, 0.f);
#pragma unroll
            for (int q = 0; q < 4; q++) xr[q] = z;
        }
    };
    auto stsA = [&](int s) {
        const uint32_t base = sb + s * STAGE_B;
        uint4 h0, h1;
        h0.x = pack_h2(xr[0].x, xr[0].y); h0.y = pack_h2(xr[0].z, xr[0].w);
        h0.z = pack_h2(xr[1].x, xr[1].y); h0.w = pack_h2(xr[1].z, xr[1].w);
        h1.x = pack_h2(xr[2].x, xr[2].y); h1.y = pack_h2(xr[2].z, xr[2].w);
        h1.z = pack_h2(xr[3].x, xr[3].y); h1.w = pack_h2(xr[3].z, xr[3].w);
        uint32_t ah = base + OFF_A + a_dso;
        asm volatile("st.shared.v4.b32 [%0], {%1,%2,%3,%4};" :: "r"(ah), "r"(h0.x), "r"(h0.y), "r"(h0.z), "r"(h0.w));
        asm volatile("st.shared.v4.b32 [%0], {%1,%2,%3,%4};" :: "r"(ah + 16), "r"(h1.x), "r"(h1.y), "r"(h1.z), "r"(h1.w));
    };

    auto cpB = [&](int c, int s) {
        const uint32_t base = sb + s * STAGE_B;
        const int kbase = c * BK;
#pragma unroll
        for (int i = tid; i < 1024; i += 256) {
            int r = i >> 2, q = i & 3;
            uint32_t dso = (uint32_t)(r * 80 + q * 16);
            size_t se = (size_t)(nbase + r) * FIN + kbase + q * 8;
            cpa16(base + OFF_B + dso, g_w1t + se);
        }
    };

    const uint32_t a_off = (uint32_t)((warp_m * 64 + (lane & 15)) * 80 + (lane >> 4) * 16);
    const uint32_t b_off = (uint32_t)((warp_n * 64 + (lane & 7) + ((lane >> 4) << 3)) * 80 +
                                      ((lane >> 3) & 1) * 16);

    float acc[4][8][4];
#pragma unroll
    for (int i = 0; i < 4; i++)
#pragma unroll
        for (int j = 0; j < 8; j++)
#pragma unroll
            for (int q = 0; q < 4; q++) acc[i][j][q] = 0.0f;

    ldA(0);
    stsA(0);
    cpB(0, 0);
    asm volatile("cp.async.commit_group;\n" ::: "memory");
    ldA(1);

    for (int c = 0; c < CHUNKS; c++) {
        const int s = c & 1;
        asm volatile("cp.async.wait_group 0;\n" ::: "memory");
        __syncthreads();

        if (c + 1 < CHUNKS) {
            stsA(s ^ 1);
            cpB(c + 1, s ^ 1);
            asm volatile("cp.async.commit_group;\n" ::: "memory");
        }
        if (c + 2 < CHUNKS) ldA(c + 2);

        const uint32_t stg = sb + s * STAGE_B;
        const uint32_t a_base = stg + OFF_A + a_off;
        const uint32_t b_base = stg + OFF_B + b_off;

#pragma unroll
        for (int kk = 0; kk < 2; kk++) {
            uint32_t av[4][4];
#pragma unroll
            for (int i = 0; i < 4; i++) {
                uint32_t ao = (uint32_t)(i * 16 * 80 + kk * 32);
                ldm_x4(a_base + ao, av[i][0], av[i][1], av[i][2], av[i][3]);
            }
#pragma unroll
            for (int j2 = 0; j2 < 4; j2++) {
                uint32_t b0, b1, b2, b3;
                uint32_t bo = (uint32_t)(j2 * 16 * 80 + kk * 32);
                ldm_x4(b_base + bo, b0, b1, b2, b3);
#pragma unroll
                for (int i = 0; i < 4; i++) {
                    float* d0 = acc[i][2 * j2];
                    float* d1 = acc[i][2 * j2 + 1];
                    mma_f16(d0[0], d0[1], d0[2], d0[3],
                            av[i][0], av[i][1], av[i][2], av[i][3], b0, b1);
                    mma_f16(d1[0], d1[1], d1[2], d1[3],
                            av[i][0], av[i][1], av[i][2], av[i][3], b2, b3);
                }
            }
        }
    }

    // epilogue: write fp16 h1
#pragma unroll
    for (int i = 0; i < 4; i++) {
        int row0 = block_row + warp_m * 64 + i * 16 + (lane >> 2);
#pragma unroll
        for (int j = 0; j < 8; j++) {
            int col = nbase + warp_n * 64 + j * 8 + (lane & 3) * 2;
            if (row0 < NN)
                *(uint32_t*)(g_h1h + (size_t)row0 * D1 + col) = pack_h2(acc[i][j][0], acc[i][j][1]);
            if (row0 + 8 < NN)
                *(uint32_t*)(g_h1h + (size_t)(row0 + 8) * D1 + col) = pack_h2(acc[i][j][2], acc[i][j][3]);
        }
    }
}

// ==================== CSR build ====================
__global__ void zero_deg_kernel() {
    int i = blockIdx.x * blockDim.x + threadIdx.x;
    if (i < NN) g_deg[i] = 0;
}

__global__ void count_kernel(const int* __restrict__ ei) {
    int e = blockIdx.x * blockDim.x + threadIdx.x;
    if (e >= ETOT) return;
    int dst = (e < EE) ? ei[EE + e] : (e - EE);
    atomicAdd(&g_deg[dst], 1);
}

__global__ __launch_bounds__(1024) void scan_kernel() {
    __shared__ int part[1024];
    const int t = threadIdx.x;
    const int CH = (NN + 1023) / 1024;
    const int base = t * CH;
    int s = 0;
    for (int i = 0; i < CH; i++) {
        int idx = base + i;
        if (idx < NN) s += g_deg[idx];
    }
    part[t] = s;
    __syncthreads();
    for (int o = 1; o < 1024; o <<= 1) {
        int v = (t >= o) ? part[t - o] : 0;
        __syncthreads();
        part[t] += v;
        __syncthreads();
    }
    int run = part[t] - s;
    for (int i = 0; i < CH; i++) {
        int idx = base + i;
        if (idx < NN) {
            g_off[idx] = run;
            g_cur[idx] = run;
            run += g_deg[idx];
        }
    }
    if (t == 1023) g_off[NN] = part[1023];
}

__global__ void scatter_kernel(const int* __restrict__ ei) {
    int e = blockIdx.x * blockDim.x + threadIdx.x;
    if (e >= ETOT) return;
    int src, dst;
    if (e < EE) { src = ei[e]; dst = ei[EE + e]; }
    else        { src = e - EE; dst = e - EE; }
    int pos = atomicAdd(&g_cur[dst], 1);
    g_srcs[pos] = src;
}

// ==================== Layer 1 alphas (fp16 h1) ====================
__global__ void alpha1_kernel(const float* __restrict__ a_s, const float* __restrict__ a_d) {
    int warp = blockIdx.x * 8 + (threadIdx.x >> 5);
    int lane = threadIdx.x & 31;
    if (warp >= NN) return;
    const __half2* row2 = (const __half2*)(g_h1h + (size_t)warp * D1);
#pragma unroll
    for (int h = 0; h < H1; h++) {
        float ss = 0.f, sd = 0.f;
#pragma unroll
        for (int k = 0; k < 2; k++) {
            int p = h * 64 + lane + 32 * k;
            float2 v = __half22float2(row2[p]);
            int c = 2 * p;
            ss = fmaf(v.x, a_s[c], ss);     ss = fmaf(v.y, a_s[c + 1], ss);
            sd = fmaf(v.x, a_d[c], sd);     sd = fmaf(v.y, a_d[c + 1], sd);
        }
#pragma unroll
        for (int o = 16; o; o >>= 1) {
            ss += __shfl_xor_sync(0xffffffffu, ss, o);
            sd += __shfl_xor_sync(0xffffffffu, sd, o);
        }
        if (lane == 0) {
            g_asrc1[warp * H1 + h] = ss;
            g_adst1[warp * H1 + h] = sd;
        }
    }
}

// ==================== Layer 1 softmax + aggregate + ELU ====================
__global__ __launch_bounds__(128) void agg1_kernel(const float* __restrict__ b1) {
    const int n = blockIdx.x;
    const int t = threadIdx.x;
    const int h = t >> 5;
    const int s0 = g_off[n];
    const int deg = g_off[n + 1] - s0;

    __shared__ float adsts[H1];
    __shared__ float sm[H1];
    __shared__ float sinv[H1];
    __shared__ float red[128 * H1];
    __shared__ int   ssrc[128];
    __shared__ float scoef[128 * H1];

    if (t < H1) adsts[t] = g_adst1[n * H1 + t];
    __syncthreads();

    const float4* asrc4 = (const float4*)g_asrc1;

    // phase 1: per-head max
    float lm[H1] = {-INFINITY, -INFINITY, -INFINITY, -INFINITY};
    for (int i = t; i < deg; i += 128) {
        float4 as = asrc4[g_srcs[s0 + i]];
        lm[0] = fmaxf(lm[0], lrelu(as.x + adsts[0]));
        lm[1] = fmaxf(lm[1], lrelu(as.y + adsts[1]));
        lm[2] = fmaxf(lm[2], lrelu(as.z + adsts[2]));
        lm[3] = fmaxf(lm[3], lrelu(as.w + adsts[3]));
    }
#pragma unroll
    for (int hh = 0; hh < H1; hh++) red[t * H1 + hh] = lm[hh];
    __syncthreads();
    if (t < H1) {
        float m = -INFINITY;
        for (int i = 0; i < 128; i++) m = fmaxf(m, red[i * H1 + t]);
        sm[t] = m;
    }
    __syncthreads();

    // phase 2: denominators
    float ls[H1] = {0.f, 0.f, 0.f, 0.f};
    for (int i = t; i < deg; i += 128) {
        float4 as = asrc4[g_srcs[s0 + i]];
        ls[0] += expf(lrelu(as.x + adsts[0]) - sm[0]);
        ls[1] += expf(lrelu(as.y + adsts[1]) - sm[1]);
        ls[2] += expf(lrelu(as.z + adsts[2]) - sm[2]);
        ls[3] += expf(lrelu(as.w + adsts[3]) - sm[3]);
    }
#pragma unroll
    for (int hh = 0; hh < H1; hh++) red[t * H1 + hh] = ls[hh];
    __syncthreads();
    if (t < H1) {
        float s = 0.f;
        for (int i = 0; i < 128; i++) s += red[i * H1 + t];
        sinv[t] = 1.0f / s;
    }
    __syncthreads();

    // phase 3: thread t owns channels [4t, 4t+4); fp16 gather
    float ax = 0.f, ay = 0.f, az = 0.f, aw = 0.f;
    for (int base = 0; base < deg; base += 128) {
        int cnt = min(128, deg - base);
        if (t < cnt) {
            int s = g_srcs[s0 + base + t];
            ssrc[t] = s;
            float4 as = asrc4[s];
            scoef[t * H1 + 0] = expf(lrelu(as.x + adsts[0]) - sm[0]) * sinv[0];
            scoef[t * H1 + 1] = expf(lrelu(as.y + adsts[1]) - sm[1]) * sinv[1];
            scoef[t * H1 + 2] = expf(lrelu(as.z + adsts[2]) - sm[2]) * sinv[2];
            scoef[t * H1 + 3] = expf(lrelu(as.w + adsts[3]) - sm[3]) * sinv[3];
        }
        __syncthreads();
        int i = 0;
        for (; i + 2 <= cnt; i += 2) {
            int sA = ssrc[i], sB = ssrc[i + 1];
            uint2 uA = *(const uint2*)(g_h1h + (size_t)sA * D1 + 4 * t);
            uint2 uB = *(const uint2*)(g_h1h + (size_t)sB * D1 + 4 * t);
            float2 a0 = __half22float2(*(__half2*)&uA.x);
            float2 a1 = __half22float2(*(__half2*)&uA.y);
            float2 b0 = __half22float2(*(__half2*)&uB.x);
            float2 b1 = __half22float2(*(__half2*)&uB.y);
            float cA = scoef[i * H1 + h];
            float cB = scoef[(i + 1) * H1 + h];
            ax = fmaf(cA, a0.x, ax); ay = fmaf(cA, a0.y, ay);
            az = fmaf(cA, a1.x, az); aw = fmaf(cA, a1.y, aw);
            ax = fmaf(cB, b0.x, ax); ay = fmaf(cB, b0.y, ay);
            az = fmaf(cB, b1.x, az); aw = fmaf(cB, b1.y, aw);
        }
        if (i < cnt) {
            uint2 u = *(const uint2*)(g_h1h + (size_t)ssrc[i] * D1 + 4 * t);
            float2 v0 = __half22float2(*(__half2*)&u.x);
            float2 v1 = __half22float2(*(__half2*)&u.y);
            float cf = scoef[i * H1 + h];
            ax = fmaf(cf, v0.x, ax); ay = fmaf(cf, v0.y, ay);
            az = fmaf(cf, v1.x, az); aw = fmaf(cf, v1.y, aw);
        }
        __syncthreads();
    }

    float4 bb = *(const float4*)(b1 + 4 * t);
    float4 o;
    o.x = ax + bb.x; o.x = o.x > 0.f ? o.x : expm1f(o.x);
    o.y = ay + bb.y; o.y = o.y > 0.f ? o.y : expm1f(o.y);
    o.z = az + bb.z; o.z = o.z > 0.f ? o.z : expm1f(o.z);
    o.w = aw + bb.w; o.w = o.w > 0.f ? o.w : expm1f(o.w);
    *(float4*)(g_out1 + (size_t)n * D1 + 4 * t) = o;
}

// ==================== Layer 2 ====================
__global__ __launch_bounds__(256) void gemm2_kernel(const float* __restrict__ W2) {
    __shared__ float w[D1 * CLS];
    int t = threadIdx.x;
    for (int i = t; i < D1 * CLS; i += 256) w[i] = W2[i];
    __syncthreads();
    int warp = blockIdx.x * 8 + (t >> 5);
    int lane = t & 31;
    if (warp >= NN) return;
    const float* row = g_out1 + (size_t)warp * D1;
    float acc[CLS] = {0.f, 0.f, 0.f, 0.f, 0.f, 0.f};
    for (int k = lane; k < D1; k += 32) {
        float v = row[k];
        const float* wr = &w[k * CLS];
#pragma unroll
        for (int c = 0; c < CLS; c++) acc[c] = fmaf(v, wr[c], acc[c]);
    }
#pragma unroll
    for (int o = 16; o; o >>= 1)
#pragma unroll
        for (int c = 0; c < CLS; c++) acc[c] += __shfl_xor_sync(0xffffffffu, acc[c], o);
    if (lane == 0) {
#pragma unroll
        for (int c = 0; c < CLS; c++) g_h2[warp * CLS + c] = acc[c];
    }
}

__global__ void alpha2_kernel(const float* __restrict__ a_s, const float* __restrict__ a_d) {
    int n = blockIdx.x * blockDim.x + threadIdx.x;
    if (n >= NN) return;
    float s = 0.f, d = 0.f;
#pragma unroll
    for (int c = 0; c < CLS; c++) {
        float v = g_h2[n * CLS + c];
        s = fmaf(v, a_s[c], s);
        d = fmaf(v, a_d[c], d);
    }
    g_as2[n] = s;
    g_ad2[n] = d;
}

__global__ __launch_bounds__(128) void agg2_kernel(const float* __restrict__ b2,
                                                   float* __restrict__ out) {
    int n = blockIdx.x * 4 + (threadIdx.x >> 5);
    int lane = threadIdx.x & 31;
    if (n >= NN) return;
    int s0 = g_off[n];
    int deg = g_off[n + 1] - s0;
    float ad = g_ad2[n];

    float lmax = -INFINITY;
    for (int i = lane; i < deg; i += 32) {
        int s = g_srcs[s0 + i];
        lmax = fmaxf(lmax, lrelu(g_as2[s] + ad));
    }
#pragma unroll
    for (int o = 16; o; o >>= 1) lmax = fmaxf(lmax, __shfl_xor_sync(0xffffffffu, lmax, o));

    float lsum = 0.f;
    for (int i = lane; i < deg; i += 32) {
        int s = g_srcs[s0 + i];
        lsum += expf(lrelu(g_as2[s] + ad) - lmax);
    }
#pragma unroll
    for (int o = 16; o; o >>= 1) lsum += __shfl_xor_sync(0xffffffffu, lsum, o);
    float inv = 1.0f / lsum;

    float acc[CLS] = {0.f, 0.f, 0.f, 0.f, 0.f, 0.f};
    for (int i = lane; i < deg; i += 32) {
        int s = g_srcs[s0 + i];
        float coef = expf(lrelu(g_as2[s] + ad) - lmax) * inv;
        const float* hp = g_h2 + s * CLS;
#pragma unroll
        for (int c = 0; c < CLS; c++) acc[c] = fmaf(coef, hp[c], acc[c]);
    }
#pragma unroll
    for (int o = 16; o; o >>= 1)
#pragma unroll
        for (int c = 0; c < CLS; c++) acc[c] += __shfl_xor_sync(0xffffffffu, acc[c], o);

    if (lane == 0) {
#pragma unroll
        for (int c = 0; c < CLS; c++) out[n * CLS + c] = acc[c] + b2[c];
    }
}

// ==================== Launch ====================
extern "C" void kernel_launch(void* const* d_in, const int* in_sizes, int n_in,
                              void* d_out, int out_size) {
    const float* x   = (const float*)d_in[0];
    const int*   ei  = (const int*)  d_in[1];
    const float* W1  = (const float*)d_in[2];
    const float* as1 = (const float*)d_in[3];
    const float* ad1 = (const float*)d_in[4];
    const float* b1  = (const float*)d_in[5];
    const float* W2  = (const float*)d_in[6];
    const float* as2 = (const float*)d_in[7];
    const float* ad2 = (const float*)d_in[8];
    const float* b2  = (const float*)d_in[9];
    float* out = (float*)d_out;

    static cudaStream_t s2 = nullptr;
    static cudaEvent_t evFork = nullptr, evJoin = nullptr;
    if (!s2) {
        cudaFuncSetAttribute(mma1_kernel, cudaFuncAttributeMaxDynamicSharedMemorySize, SMEM_SZ);
        cudaStreamCreateWithFlags(&s2, cudaStreamNonBlocking);
        cudaEventCreateWithFlags(&evFork, cudaEventDisableTiming);
        cudaEventCreateWithFlags(&evJoin, cudaEventDisableTiming);
    }

    // Fork: CSR build runs on s2, concurrent with convw1+mma1+alpha1 on main stream.
    cudaEventRecord(evFork, 0);
    cudaStreamWaitEvent(s2, evFork, 0);

    zero_deg_kernel<<<(NN + 255) / 256, 256, 0, s2>>>();
    count_kernel<<<(ETOT + 255) / 256, 256, 0, s2>>>(ei);
    scan_kernel<<<1, 1024, 0, s2>>>();
    scatter_kernel<<<(ETOT + 255) / 256, 256, 0, s2>>>(ei);
    cudaEventRecord(evJoin, s2);

    // Main stream: W1 convert -> GEMM -> alphas
    convw1_kernel<<<dim3(D1 / 32, FIN / 32), 256>>>(W1);
    mma1_kernel<<<dim3(D1 / 256, (NN + 127) / 128), 256, SMEM_SZ>>>(x);
    alpha1_kernel<<<(NN + 7) / 8, 256>>>(as1, ad1);

    // Join: agg1 needs CSR + alphas
    cudaStreamWaitEvent(0, evJoin, 0);
    agg1_kernel<<<NN, 128>>>(b1);

    // Layer 2
    gemm2_kernel<<<(NN + 7) / 8, 256>>>(W2);
    alpha2_kernel<<<(NN + 255) / 256, 256>>>(as2, ad2);
    agg2_kernel<<<(NN + 3) / 4, 128>>>(b2, out);
}

// round 12
// speedup vs baseline: 1.1320x; 1.0340x over previous
#include <cuda_runtime.h>
#include <cuda_fp16.h>
#include <math.h>
#include <stdint.h>

// ---------------- Problem constants ----------------
#define NN    30000
#define EE    480000
#define ETOT  (EE + NN)
#define FIN   4096
#define D1    512
#define H1    4
#define C1    128
#define CLS   6
#define SLOPE 0.2f
#define NEGBIG (-3.402823466e38f)

// ---------------- Device scratch ----------------
__device__ __half g_h1h[(size_t)NN * D1];   // layer-1 linear output, fp16
__device__ float g_out1[(size_t)NN * D1];   // post-attention + ELU (fp32)
__device__ float g_asrc1[NN * H1];
__device__ float g_adst1[NN * H1];
__device__ float g_h2[NN * CLS];
__device__ float g_as2[NN];
__device__ float g_ad2[NN];
__device__ int   g_deg[NN];
__device__ int   g_off[NN + 1];
__device__ int   g_cur[NN];
__device__ int   g_srcs[ETOT];

// fp16 W1 transposed: [N=512][K=4096]
__device__ __half g_w1t[(size_t)D1 * FIN];

__device__ __forceinline__ float lrelu(float v) { return v > 0.0f ? v : SLOPE * v; }

// ==================== helpers ====================
__device__ __forceinline__ uint32_t smem_u32(const void* p) {
    uint32_t a;
    asm("{ .reg .u64 t; cvta.to.shared.u64 t, %1; cvt.u32.u64 %0, t; }" : "=r"(a) : "l"(p));
    return a;
}

__device__ __forceinline__ void cpa16(uint32_t dst, const void* src) {
    asm volatile("cp.async.cg.shared.global [%0], [%1], 16;\n"
                 :: "r"(dst), "l"(src) : "memory");
}

__device__ __forceinline__ void ldm_x4(uint32_t addr, uint32_t& r0, uint32_t& r1,
                                       uint32_t& r2, uint32_t& r3) {
    asm volatile("ldmatrix.sync.aligned.m8n8.x4.shared.b16 {%0,%1,%2,%3}, [%4];"
                 : "=r"(r0), "=r"(r1), "=r"(r2), "=r"(r3) : "r"(addr));
}

__device__ __forceinline__ void mma_f16(float& d0, float& d1, float& d2, float& d3,
                                        uint32_t a0, uint32_t a1, uint32_t a2, uint32_t a3,
                                        uint32_t b0, uint32_t b1) {
    asm volatile("mma.sync.aligned.m16n8k16.row.col.f32.f16.f16.f32 "
                 "{%0,%1,%2,%3}, {%4,%5,%6,%7}, {%8,%9}, {%0,%1,%2,%3};"
                 : "+f"(d0), "+f"(d1), "+f"(d2), "+f"(d3)
                 : "r"(a0), "r"(a1), "r"(a2), "r"(a3), "r"(b0), "r"(b1));
}

__device__ __forceinline__ uint32_t pack_h2(float a, float b) {
    __half2 h = __halves2half2(__float2half_rn(a), __float2half_rn(b));
    return *(uint32_t*)&h;
}

// ==================== W1 -> fp16 transposed (32x32 tile) ====================
__global__ __launch_bounds__(256) void convw1_kernel(const float* __restrict__ W1) {
    __shared__ float tile[32][33];
    const int kb = blockIdx.y * 32;
    const int nb = blockIdx.x * 32;
    const int t = threadIdx.x;
    const int r = t >> 5, c = t & 31;
#pragma unroll
    for (int rr = r; rr < 32; rr += 8)
        tile[rr][c] = W1[(size_t)(kb + rr) * D1 + nb + c];
    __syncthreads();
#pragma unroll
    for (int rr = r; rr < 32; rr += 8) {
        float v = tile[c][rr];
        g_w1t[(size_t)(nb + rr) * FIN + kb + c] = __float2half_rn(v);
    }
}

// ==================== GEMM1: fused-convert fp16 mma.sync, 128x256 tile ====================
#define BK       32
#define CHUNKS   (FIN / BK)      // 128
#define TILE_A_B (128 * 80)      // 10240
#define TILE_B_B (256 * 80)      // 20480
#define OFF_A    0
#define OFF_B    (TILE_A_B)
#define STAGE_B  (TILE_A_B + TILE_B_B)   // 30720
#define SMEM_SZ  (2 * STAGE_B)           // 61440

__global__ __launch_bounds__(256) void mma1_kernel(const float* __restrict__ x) {
    extern __shared__ __align__(16) char dsm[];
    const uint32_t sb = smem_u32(dsm);

    const int tid = threadIdx.x;
    const int wid = tid >> 5;
    const int lane = tid & 31;
    const int warp_m = wid >> 2;    // 0..1
    const int warp_n = wid & 3;     // 0..3
    const int block_row = blockIdx.y * 128;
    const int nbase = blockIdx.x * 256;

    const int a_r = tid >> 1;
    const int a_half = tid & 1;
    const bool a_ok = (block_row + a_r) < NN;
    const float* a_src = x + (size_t)(block_row + a_r) * FIN + a_half * 16;
    const uint32_t a_dso = (uint32_t)(a_r * 80 + a_half * 32);

    float4 xr[4];
    auto ldA = [&](int c) {
        if (a_ok) {
            const float4* p = (const float4*)(a_src + c * BK);
#pragma unroll
            for (int q = 0; q < 4; q++) xr[q] = p[q];
        } else {
            float4 z = make_float4(0.f, 0.f, 0.f, 0.f);
#pragma unroll
            for (int q = 0; q < 4; q++) xr[q] = z;
        }
    };
    auto stsA = [&](int s) {
        const uint32_t base = sb + s * STAGE_B;
        uint4 h0, h1;
        h0.x = pack_h2(xr[0].x, xr[0].y); h0.y = pack_h2(xr[0].z, xr[0].w);
        h0.z = pack_h2(xr[1].x, xr[1].y); h0.w = pack_h2(xr[1].z, xr[1].w);
        h1.x = pack_h2(xr[2].x, xr[2].y); h1.y = pack_h2(xr[2].z, xr[2].w);
        h1.z = pack_h2(xr[3].x, xr[3].y); h1.w = pack_h2(xr[3].z, xr[3].w);
        uint32_t ah = base + OFF_A + a_dso;
        asm volatile("st.shared.v4.b32 [%0], {%1,%2,%3,%4};" :: "r"(ah), "r"(h0.x), "r"(h0.y), "r"(h0.z), "r"(h0.w));
        asm volatile("st.shared.v4.b32 [%0], {%1,%2,%3,%4};" :: "r"(ah + 16), "r"(h1.x), "r"(h1.y), "r"(h1.z), "r"(h1.w));
    };

    auto cpB = [&](int c, int s) {
        const uint32_t base = sb + s * STAGE_B;
        const int kbase = c * BK;
#pragma unroll
        for (int i = tid; i < 1024; i += 256) {
            int r = i >> 2, q = i & 3;
            uint32_t dso = (uint32_t)(r * 80 + q * 16);
            size_t se = (size_t)(nbase + r) * FIN + kbase + q * 8;
            cpa16(base + OFF_B + dso, g_w1t + se);
        }
    };

    const uint32_t a_off = (uint32_t)((warp_m * 64 + (lane & 15)) * 80 + (lane >> 4) * 16);
    const uint32_t b_off = (uint32_t)((warp_n * 64 + (lane & 7) + ((lane >> 4) << 3)) * 80 +
                                      ((lane >> 3) & 1) * 16);

    float acc[4][8][4];
#pragma unroll
    for (int i = 0; i < 4; i++)
#pragma unroll
        for (int j = 0; j < 8; j++)
#pragma unroll
            for (int q = 0; q < 4; q++) acc[i][j][q] = 0.0f;

    ldA(0);
    stsA(0);
    cpB(0, 0);
    asm volatile("cp.async.commit_group;\n" ::: "memory");
    ldA(1);

    for (int c = 0; c < CHUNKS; c++) {
        const int s = c & 1;
        asm volatile("cp.async.wait_group 0;\n" ::: "memory");
        __syncthreads();

        if (c + 1 < CHUNKS) {
            stsA(s ^ 1);
            cpB(c + 1, s ^ 1);
            asm volatile("cp.async.commit_group;\n" ::: "memory");
        }
        if (c + 2 < CHUNKS) ldA(c + 2);

        const uint32_t stg = sb + s * STAGE_B;
        const uint32_t a_base = stg + OFF_A + a_off;
        const uint32_t b_base = stg + OFF_B + b_off;

#pragma unroll
        for (int kk = 0; kk < 2; kk++) {
            uint32_t av[4][4];
#pragma unroll
            for (int i = 0; i < 4; i++) {
                uint32_t ao = (uint32_t)(i * 16 * 80 + kk * 32);
                ldm_x4(a_base + ao, av[i][0], av[i][1], av[i][2], av[i][3]);
            }
#pragma unroll
            for (int j2 = 0; j2 < 4; j2++) {
                uint32_t b0, b1, b2, b3;
                uint32_t bo = (uint32_t)(j2 * 16 * 80 + kk * 32);
                ldm_x4(b_base + bo, b0, b1, b2, b3);
#pragma unroll
                for (int i = 0; i < 4; i++) {
                    float* d0 = acc[i][2 * j2];
                    float* d1 = acc[i][2 * j2 + 1];
                    mma_f16(d0[0], d0[1], d0[2], d0[3],
                            av[i][0], av[i][1], av[i][2], av[i][3], b0, b1);
                    mma_f16(d1[0], d1[1], d1[2], d1[3],
                            av[i][0], av[i][1], av[i][2], av[i][3], b2, b3);
                }
            }
        }
    }

    // epilogue: write fp16 h1
#pragma unroll
    for (int i = 0; i < 4; i++) {
        int row0 = block_row + warp_m * 64 + i * 16 + (lane >> 2);
#pragma unroll
        for (int j = 0; j < 8; j++) {
            int col = nbase + warp_n * 64 + j * 8 + (lane & 3) * 2;
            if (row0 < NN)
                *(uint32_t*)(g_h1h + (size_t)row0 * D1 + col) = pack_h2(acc[i][j][0], acc[i][j][1]);
            if (row0 + 8 < NN)
                *(uint32_t*)(g_h1h + (size_t)(row0 + 8) * D1 + col) = pack_h2(acc[i][j][2], acc[i][j][3]);
        }
    }
}

// ==================== CSR build ====================
__global__ void zero_deg_kernel() {
    int i = blockIdx.x * blockDim.x + threadIdx.x;
    if (i < NN) g_deg[i] = 0;
}

__global__ void count_kernel(const int* __restrict__ ei) {
    int e = blockIdx.x * blockDim.x + threadIdx.x;
    if (e >= ETOT) return;
    int dst = (e < EE) ? ei[EE + e] : (e - EE);
    atomicAdd(&g_deg[dst], 1);
}

__global__ __launch_bounds__(1024) void scan_kernel() {
    __shared__ int part[1024];
    const int t = threadIdx.x;
    const int CH = (NN + 1023) / 1024;
    const int base = t * CH;
    int s = 0;
    for (int i = 0; i < CH; i++) {
        int idx = base + i;
        if (idx < NN) s += g_deg[idx];
    }
    part[t] = s;
    __syncthreads();
    for (int o = 1; o < 1024; o <<= 1) {
        int v = (t >= o) ? part[t - o] : 0;
        __syncthreads();
        part[t] += v;
        __syncthreads();
    }
    int run = part[t] - s;
    for (int i = 0; i < CH; i++) {
        int idx = base + i;
        if (idx < NN) {
            g_off[idx] = run;
            g_cur[idx] = run;
            run += g_deg[idx];
        }
    }
    if (t == 1023) g_off[NN] = part[1023];
}

__global__ void scatter_kernel(const int* __restrict__ ei) {
    int e = blockIdx.x * blockDim.x + threadIdx.x;
    if (e >= ETOT) return;
    int src, dst;
    if (e < EE) { src = ei[e]; dst = ei[EE + e]; }
    else        { src = e - EE; dst = e - EE; }
    int pos = atomicAdd(&g_cur[dst], 1);
    g_srcs[pos] = src;
}

// ==================== Layer 1 alphas (fp16 h1) ====================
__global__ void alpha1_kernel(const float* __restrict__ a_s, const float* __restrict__ a_d) {
    int warp = blockIdx.x * 8 + (threadIdx.x >> 5);
    int lane = threadIdx.x & 31;
    if (warp >= NN) return;
    const __half2* row2 = (const __half2*)(g_h1h + (size_t)warp * D1);
#pragma unroll
    for (int h = 0; h < H1; h++) {
        float ss = 0.f, sd = 0.f;
#pragma unroll
        for (int k = 0; k < 2; k++) {
            int p = h * 64 + lane + 32 * k;
            float2 v = __half22float2(row2[p]);
            int c = 2 * p;
            ss = fmaf(v.x, a_s[c], ss);     ss = fmaf(v.y, a_s[c + 1], ss);
            sd = fmaf(v.x, a_d[c], sd);     sd = fmaf(v.y, a_d[c + 1], sd);
        }
#pragma unroll
        for (int o = 16; o; o >>= 1) {
            ss += __shfl_xor_sync(0xffffffffu, ss, o);
            sd += __shfl_xor_sync(0xffffffffu, sd, o);
        }
        if (lane == 0) {
            g_asrc1[warp * H1 + h] = ss;
            g_adst1[warp * H1 + h] = sd;
        }
    }
}

// ==================== Layer 1: warp-per-node softmax + aggregate + ELU ====================
__global__ __launch_bounds__(256) void agg1_kernel(const float* __restrict__ b1) {
    const int n = blockIdx.x * 8 + (threadIdx.x >> 5);
    const int lane = threadIdx.x & 31;
    if (n >= NN) return;
    const int s0 = g_off[n];
    const int deg = g_off[n + 1] - s0;
    const int h = lane >> 3;     // head owned by this lane's 16 channels

    const float4* asrc4 = (const float4*)g_asrc1;
    float4 ad4 = *(const float4*)(g_adst1 + n * H1);
    float ad[H1] = {ad4.x, ad4.y, ad4.z, ad4.w};

    // pass 1: online (max, sum) per head over this lane's edge subset
    float m[H1] = {NEGBIG, NEGBIG, NEGBIG, NEGBIG};
    float sa[H1] = {0.f, 0.f, 0.f, 0.f};
    for (int i = lane; i < deg; i += 32) {
        float4 as = asrc4[g_srcs[s0 + i]];
        float l[H1];
        l[0] = lrelu(as.x + ad[0]);
        l[1] = lrelu(as.y + ad[1]);
        l[2] = lrelu(as.z + ad[2]);
        l[3] = lrelu(as.w + ad[3]);
#pragma unroll
        for (int hh = 0; hh < H1; hh++) {
            float M = fmaxf(m[hh], l[hh]);
            sa[hh] = sa[hh] * expf(m[hh] - M) + expf(l[hh] - M);
            m[hh] = M;
        }
    }
#pragma unroll
    for (int o = 16; o; o >>= 1) {
#pragma unroll
        for (int hh = 0; hh < H1; hh++) {
            float mo = __shfl_xor_sync(0xffffffffu, m[hh], o);
            float so = __shfl_xor_sync(0xffffffffu, sa[hh], o);
            float M = fmaxf(m[hh], mo);
            sa[hh] = sa[hh] * expf(m[hh] - M) + so * expf(mo - M);
            m[hh] = M;
        }
    }
    const float Mh = m[h];
    const float SINV = 1.0f / sa[h];
    const float adh = ad[h];

    // pass 2: aggregate 16 channels per lane (channels [16*lane, 16*lane+16))
    float acc[16];
#pragma unroll
    for (int q = 0; q < 16; q++) acc[q] = 0.f;

    const __half* hb = g_h1h + 16 * lane;
    for (int i = 0; i < deg; i++) {
        int s = g_srcs[s0 + i];                          // warp-uniform
        float asv = __ldg(&g_asrc1[s * H1 + h]);         // 8-way broadcast
        float coef = expf(lrelu(asv + adh) - Mh) * SINV;
        const uint4* p = (const uint4*)(hb + (size_t)s * D1);
        uint4 u0 = p[0];
        uint4 u1 = p[1];
        const __half2* c0 = (const __half2*)&u0;
        const __half2* c1 = (const __half2*)&u1;
#pragma unroll
        for (int q = 0; q < 4; q++) {
            float2 v0 = __half22float2(c0[q]);
            float2 v1 = __half22float2(c1[q]);
            acc[2 * q + 0] = fmaf(coef, v0.x, acc[2 * q + 0]);
            acc[2 * q + 1] = fmaf(coef, v0.y, acc[2 * q + 1]);
            acc[8 + 2 * q + 0] = fmaf(coef, v1.x, acc[8 + 2 * q + 0]);
            acc[8 + 2 * q + 1] = fmaf(coef, v1.y, acc[8 + 2 * q + 1]);
        }
    }

    // bias + ELU, write 16 floats
    float* orow = g_out1 + (size_t)n * D1 + 16 * lane;
    const float* bp = b1 + 16 * lane;
#pragma unroll
    for (int q4 = 0; q4 < 4; q4++) {
        float4 bb = *(const float4*)(bp + 4 * q4);
        float4 o;
        o.x = acc[4 * q4 + 0] + bb.x; o.x = o.x > 0.f ? o.x : expm1f(o.x);
        o.y = acc[4 * q4 + 1] + bb.y; o.y = o.y > 0.f ? o.y : expm1f(o.y);
        o.z = acc[4 * q4 + 2] + bb.z; o.z = o.z > 0.f ? o.z : expm1f(o.z);
        o.w = acc[4 * q4 + 3] + bb.w; o.w = o.w > 0.f ? o.w : expm1f(o.w);
        *(float4*)(orow + 4 * q4) = o;
    }
}

// ==================== Layer 2 ====================
__global__ __launch_bounds__(256) void gemm2_kernel(const float* __restrict__ W2) {
    __shared__ float w[D1 * CLS];
    int t = threadIdx.x;
    for (int i = t; i < D1 * CLS; i += 256) w[i] = W2[i];
    __syncthreads();
    int warp = blockIdx.x * 8 + (t >> 5);
    int lane = t & 31;
    if (warp >= NN) return;
    const float* row = g_out1 + (size_t)warp * D1;
    float acc[CLS] = {0.f, 0.f, 0.f, 0.f, 0.f, 0.f};
    for (int k = lane; k < D1; k += 32) {
        float v = row[k];
        const float* wr = &w[k * CLS];
#pragma unroll
        for (int c = 0; c < CLS; c++) acc[c] = fmaf(v, wr[c], acc[c]);
    }
#pragma unroll
    for (int o = 16; o; o >>= 1)
#pragma unroll
        for (int c = 0; c < CLS; c++) acc[c] += __shfl_xor_sync(0xffffffffu, acc[c], o);
    if (lane == 0) {
#pragma unroll
        for (int c = 0; c < CLS; c++) g_h2[warp * CLS + c] = acc[c];
    }
}

__global__ void alpha2_kernel(const float* __restrict__ a_s, const float* __restrict__ a_d) {
    int n = blockIdx.x * blockDim.x + threadIdx.x;
    if (n >= NN) return;
    float s = 0.f, d = 0.f;
#pragma unroll
    for (int c = 0; c < CLS; c++) {
        float v = g_h2[n * CLS + c];
        s = fmaf(v, a_s[c], s);
        d = fmaf(v, a_d[c], d);
    }
    g_as2[n] = s;
    g_ad2[n] = d;
}

__global__ __launch_bounds__(128) void agg2_kernel(const float* __restrict__ b2,
                                                   float* __restrict__ out) {
    int n = blockIdx.x * 4 + (threadIdx.x >> 5);
    int lane = threadIdx.x & 31;
    if (n >= NN) return;
    int s0 = g_off[n];
    int deg = g_off[n + 1] - s0;
    float ad = g_ad2[n];

    float lmax = -INFINITY;
    for (int i = lane; i < deg; i += 32) {
        int s = g_srcs[s0 + i];
        lmax = fmaxf(lmax, lrelu(g_as2[s] + ad));
    }
#pragma unroll
    for (int o = 16; o; o >>= 1) lmax = fmaxf(lmax, __shfl_xor_sync(0xffffffffu, lmax, o));

    float lsum = 0.f;
    for (int i = lane; i < deg; i += 32) {
        int s = g_srcs[s0 + i];
        lsum += expf(lrelu(g_as2[s] + ad) - lmax);
    }
#pragma unroll
    for (int o = 16; o; o >>= 1) lsum += __shfl_xor_sync(0xffffffffu, lsum, o);
    float inv = 1.0f / lsum;

    float acc[CLS] = {0.f, 0.f, 0.f, 0.f, 0.f, 0.f};
    for (int i = lane; i < deg; i += 32) {
        int s = g_srcs[s0 + i];
        float coef = expf(lrelu(g_as2[s] + ad) - lmax) * inv;
        const float* hp = g_h2 + s * CLS;
#pragma unroll
        for (int c = 0; c < CLS; c++) acc[c] = fmaf(coef, hp[c], acc[c]);
    }
#pragma unroll
    for (int o = 16; o; o >>= 1)
#pragma unroll
        for (int c = 0; c < CLS; c++) acc[c] += __shfl_xor_sync(0xffffffffu, acc[c], o);

    if (lane == 0) {
#pragma unroll
        for (int c = 0; c < CLS; c++) out[n * CLS + c] = acc[c] + b2[c];
    }
}

// ==================== Launch ====================
extern "C" void kernel_launch(void* const* d_in, const int* in_sizes, int n_in,
                              void* d_out, int out_size) {
    const float* x   = (const float*)d_in[0];
    const int*   ei  = (const int*)  d_in[1];
    const float* W1  = (const float*)d_in[2];
    const float* as1 = (const float*)d_in[3];
    const float* ad1 = (const float*)d_in[4];
    const float* b1  = (const float*)d_in[5];
    const float* W2  = (const float*)d_in[6];
    const float* as2 = (const float*)d_in[7];
    const float* ad2 = (const float*)d_in[8];
    const float* b2  = (const float*)d_in[9];
    float* out = (float*)d_out;

    static cudaStream_t s2 = nullptr;
    static cudaEvent_t evFork = nullptr, evJoin = nullptr;
    if (!s2) {
        cudaFuncSetAttribute(mma1_kernel, cudaFuncAttributeMaxDynamicSharedMemorySize, SMEM_SZ);
        cudaStreamCreateWithFlags(&s2, cudaStreamNonBlocking);
        cudaEventCreateWithFlags(&evFork, cudaEventDisableTiming);
        cudaEventCreateWithFlags(&evJoin, cudaEventDisableTiming);
    }

    // Fork: CSR build runs on s2, concurrent with convw1+mma1+alpha1 on main stream.
    cudaEventRecord(evFork, 0);
    cudaStreamWaitEvent(s2, evFork, 0);

    zero_deg_kernel<<<(NN + 255) / 256, 256, 0, s2>>>();
    count_kernel<<<(ETOT + 255) / 256, 256, 0, s2>>>(ei);
    scan_kernel<<<1, 1024, 0, s2>>>();
    scatter_kernel<<<(ETOT + 255) / 256, 256, 0, s2>>>(ei);
    cudaEventRecord(evJoin, s2);

    // Main stream: W1 convert -> GEMM -> alphas
    convw1_kernel<<<dim3(D1 / 32, FIN / 32), 256>>>(W1);
    mma1_kernel<<<dim3(D1 / 256, (NN + 127) / 128), 256, SMEM_SZ>>>(x);
    alpha1_kernel<<<(NN + 7) / 8, 256>>>(as1, ad1);

    // Join: agg1 needs CSR + alphas
    cudaStreamWaitEvent(0, evJoin, 0);
    agg1_kernel<<<(NN + 7) / 8, 256>>>(b1);

    // Layer 2
    gemm2_kernel<<<(NN + 7) / 8, 256>>>(W2);
    alpha2_kernel<<<(NN + 255) / 256, 256>>>(as2, ad2);
    agg2_kernel<<<(NN + 3) / 4, 128>>>(b2, out);
}

// round 13
// speedup vs baseline: 1.1582x; 1.0231x over previous
#include <cuda_runtime.h>
#include <cuda_fp16.h>
#include <math.h>
#include <stdint.h>

// ---------------- Problem constants ----------------
#define NN    30000
#define EE    480000
#define ETOT  (EE + NN)
#define FIN   4096
#define D1    512
#define H1    4
#define C1    128
#define CLS   6
#define SLOPE 0.2f
#define NEGBIG (-3.402823466e38f)

// ---------------- Device scratch ----------------
__device__ __half g_h1h[(size_t)NN * D1];   // layer-1 linear output, fp16
__device__ float g_out1[(size_t)NN * D1];   // post-attention + ELU (fp32)
__device__ float g_asrc1[NN * H1];
__device__ float g_adst1[NN * H1];
__device__ float g_h2[NN * CLS];
__device__ float g_as2[NN];
__device__ float g_ad2[NN];
__device__ int   g_deg[NN];
__device__ int   g_off[NN + 1];
__device__ int   g_cur[NN];
__device__ int   g_srcs[ETOT];

// fp16 W1 transposed: [N=512][K=4096]
__device__ __half g_w1t[(size_t)D1 * FIN];

__device__ __forceinline__ float lrelu(float v) { return v > 0.0f ? v : SLOPE * v; }

// ==================== helpers ====================
__device__ __forceinline__ uint32_t smem_u32(const void* p) {
    uint32_t a;
    asm("{ .reg .u64 t; cvta.to.shared.u64 t, %1; cvt.u32.u64 %0, t; }" : "=r"(a) : "l"(p));
    return a;
}

__device__ __forceinline__ void cpa16(uint32_t dst, const void* src) {
    asm volatile("cp.async.cg.shared.global [%0], [%1], 16;\n"
                 :: "r"(dst), "l"(src) : "memory");
}

__device__ __forceinline__ void ldm_x4(uint32_t addr, uint32_t& r0, uint32_t& r1,
                                       uint32_t& r2, uint32_t& r3) {
    asm volatile("ldmatrix.sync.aligned.m8n8.x4.shared.b16 {%0,%1,%2,%3}, [%4];"
                 : "=r"(r0), "=r"(r1), "=r"(r2), "=r"(r3) : "r"(addr));
}

__device__ __forceinline__ void mma_f16(float& d0, float& d1, float& d2, float& d3,
                                        uint32_t a0, uint32_t a1, uint32_t a2, uint32_t a3,
                                        uint32_t b0, uint32_t b1) {
    asm volatile("mma.sync.aligned.m16n8k16.row.col.f32.f16.f16.f32 "
                 "{%0,%1,%2,%3}, {%4,%5,%6,%7}, {%8,%9}, {%0,%1,%2,%3};"
                 : "+f"(d0), "+f"(d1), "+f"(d2), "+f"(d3)
                 : "r"(a0), "r"(a1), "r"(a2), "r"(a3), "r"(b0), "r"(b1));
}

__device__ __forceinline__ uint32_t pack_h2(float a, float b) {
    __half2 h = __halves2half2(__float2half_rn(a), __float2half_rn(b));
    return *(uint32_t*)&h;
}

// ==================== W1 -> fp16 transposed (32x32 tile) ====================
__global__ __launch_bounds__(256) void convw1_kernel(const float* __restrict__ W1) {
    __shared__ float tile[32][33];
    const int kb = blockIdx.y * 32;
    const int nb = blockIdx.x * 32;
    const int t = threadIdx.x;
    const int r = t >> 5, c = t & 31;
#pragma unroll
    for (int rr = r; rr < 32; rr += 8)
        tile[rr][c] = W1[(size_t)(kb + rr) * D1 + nb + c];
    __syncthreads();
#pragma unroll
    for (int rr = r; rr < 32; rr += 8) {
        float v = tile[c][rr];
        g_w1t[(size_t)(nb + rr) * FIN + kb + c] = __float2half_rn(v);
    }
}

// ==================== GEMM1 + fused alpha1: fp16 mma.sync, 128x256 tile ====================
#define BK       32
#define CHUNKS   (FIN / BK)      // 128
#define TILE_A_B (128 * 80)      // 10240
#define TILE_B_B (256 * 80)      // 20480
#define OFF_A    0
#define OFF_B    (TILE_A_B)
#define STAGE_B  (TILE_A_B + TILE_B_B)   // 30720
#define SMEM_SZ  (2 * STAGE_B)           // 61440

__global__ __launch_bounds__(256) void mma1_kernel(const float* __restrict__ x,
                                                   const float* __restrict__ a_s,
                                                   const float* __restrict__ a_d) {
    extern __shared__ __align__(16) char dsm[];
    const uint32_t sb = smem_u32(dsm);
    __shared__ float s_as[256];
    __shared__ float s_ad[256];

    const int tid = threadIdx.x;
    const int wid = tid >> 5;
    const int lane = tid & 31;
    const int warp_m = wid >> 2;    // 0..1
    const int warp_n = wid & 3;     // 0..3
    const int block_row = blockIdx.y * 128;
    const int nbase = blockIdx.x * 256;

    // stage attention vectors for this CTA's 256 columns
    s_as[tid] = a_s[nbase + tid];
    s_ad[tid] = a_d[nbase + tid];

    const int a_r = tid >> 1;
    const int a_half = tid & 1;
    const bool a_ok = (block_row + a_r) < NN;
    const float* a_src = x + (size_t)(block_row + a_r) * FIN + a_half * 16;
    const uint32_t a_dso = (uint32_t)(a_r * 80 + a_half * 32);

    float4 xr[4];
    auto ldA = [&](int c) {
        if (a_ok) {
            const float4* p = (const float4*)(a_src + c * BK);
#pragma unroll
            for (int q = 0; q < 4; q++) xr[q] = p[q];
        } else {
            float4 z = make_float4(0.f, 0.f, 0.f, 0.f);
#pragma unroll
            for (int q = 0; q < 4; q++) xr[q] = z;
        }
    };
    auto stsA = [&](int s) {
        const uint32_t base = sb + s * STAGE_B;
        uint4 h0, h1;
        h0.x = pack_h2(xr[0].x, xr[0].y); h0.y = pack_h2(xr[0].z, xr[0].w);
        h0.z = pack_h2(xr[1].x, xr[1].y); h0.w = pack_h2(xr[1].z, xr[1].w);
        h1.x = pack_h2(xr[2].x, xr[2].y); h1.y = pack_h2(xr[2].z, xr[2].w);
        h1.z = pack_h2(xr[3].x, xr[3].y); h1.w = pack_h2(xr[3].z, xr[3].w);
        uint32_t ah = base + OFF_A + a_dso;
        asm volatile("st.shared.v4.b32 [%0], {%1,%2,%3,%4};" :: "r"(ah), "r"(h0.x), "r"(h0.y), "r"(h0.z), "r"(h0.w));
        asm volatile("st.shared.v4.b32 [%0], {%1,%2,%3,%4};" :: "r"(ah + 16), "r"(h1.x), "r"(h1.y), "r"(h1.z), "r"(h1.w));
    };

    auto cpB = [&](int c, int s) {
        const uint32_t base = sb + s * STAGE_B;
        const int kbase = c * BK;
#pragma unroll
        for (int i = tid; i < 1024; i += 256) {
            int r = i >> 2, q = i & 3;
            uint32_t dso = (uint32_t)(r * 80 + q * 16);
            size_t se = (size_t)(nbase + r) * FIN + kbase + q * 8;
            cpa16(base + OFF_B + dso, g_w1t + se);
        }
    };

    const uint32_t a_off = (uint32_t)((warp_m * 64 + (lane & 15)) * 80 + (lane >> 4) * 16);
    const uint32_t b_off = (uint32_t)((warp_n * 64 + (lane & 7) + ((lane >> 4) << 3)) * 80 +
                                      ((lane >> 3) & 1) * 16);

    float acc[4][8][4];
#pragma unroll
    for (int i = 0; i < 4; i++)
#pragma unroll
        for (int j = 0; j < 8; j++)
#pragma unroll
            for (int q = 0; q < 4; q++) acc[i][j][q] = 0.0f;

    ldA(0);
    stsA(0);
    cpB(0, 0);
    asm volatile("cp.async.commit_group;\n" ::: "memory");
    ldA(1);

    for (int c = 0; c < CHUNKS; c++) {
        const int s = c & 1;
        asm volatile("cp.async.wait_group 0;\n" ::: "memory");
        __syncthreads();

        if (c + 1 < CHUNKS) {
            stsA(s ^ 1);
            cpB(c + 1, s ^ 1);
            asm volatile("cp.async.commit_group;\n" ::: "memory");
        }
        if (c + 2 < CHUNKS) ldA(c + 2);

        const uint32_t stg = sb + s * STAGE_B;
        const uint32_t a_base = stg + OFF_A + a_off;
        const uint32_t b_base = stg + OFF_B + b_off;

#pragma unroll
        for (int kk = 0; kk < 2; kk++) {
            uint32_t av[4][4];
#pragma unroll
            for (int i = 0; i < 4; i++) {
                uint32_t ao = (uint32_t)(i * 16 * 80 + kk * 32);
                ldm_x4(a_base + ao, av[i][0], av[i][1], av[i][2], av[i][3]);
            }
#pragma unroll
            for (int j2 = 0; j2 < 4; j2++) {
                uint32_t b0, b1, b2, b3;
                uint32_t bo = (uint32_t)(j2 * 16 * 80 + kk * 32);
                ldm_x4(b_base + bo, b0, b1, b2, b3);
#pragma unroll
                for (int i = 0; i < 4; i++) {
                    float* d0 = acc[i][2 * j2];
                    float* d1 = acc[i][2 * j2 + 1];
                    mma_f16(d0[0], d0[1], d0[2], d0[3],
                            av[i][0], av[i][1], av[i][2], av[i][3], b0, b1);
                    mma_f16(d1[0], d1[1], d1[2], d1[3],
                            av[i][0], av[i][1], av[i][2], av[i][3], b2, b3);
                }
            }
        }
    }

    // make stage smem safe to reuse for alpha partials
    __syncthreads();
    float* psred = (float*)dsm;          // [2][4][64] = 512 floats
    float* pdred = psred + 512;          // [2][4][64]

    // epilogue: write fp16 h1 + per-warp alpha partials into smem
#pragma unroll
    for (int i = 0; i < 4; i++) {
        int row0 = block_row + warp_m * 64 + i * 16 + (lane >> 2);
        float ps0 = 0.f, pd0 = 0.f, ps1 = 0.f, pd1 = 0.f;
#pragma unroll
        for (int j = 0; j < 8; j++) {
            int cl = warp_n * 64 + j * 8 + (lane & 3) * 2;   // column within CTA tile
            int col = nbase + cl;
            if (row0 < NN)
                *(uint32_t*)(g_h1h + (size_t)row0 * D1 + col) = pack_h2(acc[i][j][0], acc[i][j][1]);
            if (row0 + 8 < NN)
                *(uint32_t*)(g_h1h + (size_t)(row0 + 8) * D1 + col) = pack_h2(acc[i][j][2], acc[i][j][3]);
            float as0 = s_as[cl], as1 = s_as[cl + 1];
            float ad0 = s_ad[cl], ad1 = s_ad[cl + 1];
            ps0 = fmaf(acc[i][j][0], as0, ps0); ps0 = fmaf(acc[i][j][1], as1, ps0);
            pd0 = fmaf(acc[i][j][0], ad0, pd0); pd0 = fmaf(acc[i][j][1], ad1, pd0);
            ps1 = fmaf(acc[i][j][2], as0, ps1); ps1 = fmaf(acc[i][j][3], as1, ps1);
            pd1 = fmaf(acc[i][j][2], ad0, pd1); pd1 = fmaf(acc[i][j][3], ad1, pd1);
        }
#pragma unroll
        for (int o = 1; o <= 2; o <<= 1) {
            ps0 += __shfl_xor_sync(0xffffffffu, ps0, o);
            pd0 += __shfl_xor_sync(0xffffffffu, pd0, o);
            ps1 += __shfl_xor_sync(0xffffffffu, ps1, o);
            pd1 += __shfl_xor_sync(0xffffffffu, pd1, o);
        }
        if ((lane & 3) == 0) {
            int r64 = i * 16 + (lane >> 2);
            int bidx = (warp_m * 4 + warp_n) * 64;
            psred[bidx + r64] = ps0;
            pdred[bidx + r64] = pd0;
            psred[bidx + r64 + 8] = ps1;
            pdred[bidx + r64 + 8] = pd1;
        }
    }
    __syncthreads();

    // final reduce over warp_n pairs; one plain store per (row, head)
    {
        int wm = tid >> 7;            // 0..1
        int hl = (tid >> 6) & 1;      // head-local 0..1
        int r = tid & 63;
        int row = block_row + wm * 64 + r;
        if (row < NN) {
            int b0 = (wm * 4 + 2 * hl) * 64 + r;
            int b1 = (wm * 4 + 2 * hl + 1) * 64 + r;
            int head = (nbase >> 7) + hl;
            g_asrc1[row * H1 + head] = psred[b0] + psred[b1];
            g_adst1[row * H1 + head] = pdred[b0] + pdred[b1];
        }
    }
}

// ==================== CSR build ====================
__global__ void zero_deg_kernel() {
    int i = blockIdx.x * blockDim.x + threadIdx.x;
    if (i < NN) g_deg[i] = 0;
}

__global__ void count_kernel(const int* __restrict__ ei) {
    int e = blockIdx.x * blockDim.x + threadIdx.x;
    if (e >= ETOT) return;
    int dst = (e < EE) ? ei[EE + e] : (e - EE);
    atomicAdd(&g_deg[dst], 1);
}

__global__ __launch_bounds__(1024) void scan_kernel() {
    __shared__ int part[1024];
    const int t = threadIdx.x;
    const int CH = (NN + 1023) / 1024;
    const int base = t * CH;
    int s = 0;
    for (int i = 0; i < CH; i++) {
        int idx = base + i;
        if (idx < NN) s += g_deg[idx];
    }
    part[t] = s;
    __syncthreads();
    for (int o = 1; o < 1024; o <<= 1) {
        int v = (t >= o) ? part[t - o] : 0;
        __syncthreads();
        part[t] += v;
        __syncthreads();
    }
    int run = part[t] - s;
    for (int i = 0; i < CH; i++) {
        int idx = base + i;
        if (idx < NN) {
            g_off[idx] = run;
            g_cur[idx] = run;
            run += g_deg[idx];
        }
    }
    if (t == 1023) g_off[NN] = part[1023];
}

__global__ void scatter_kernel(const int* __restrict__ ei) {
    int e = blockIdx.x * blockDim.x + threadIdx.x;
    if (e >= ETOT) return;
    int src, dst;
    if (e < EE) { src = ei[e]; dst = ei[EE + e]; }
    else        { src = e - EE; dst = e - EE; }
    int pos = atomicAdd(&g_cur[dst], 1);
    g_srcs[pos] = src;
}

// ==================== Layer 1: warp-per-node softmax + aggregate + ELU ====================
__global__ __launch_bounds__(256) void agg1_kernel(const float* __restrict__ b1) {
    const int n = blockIdx.x * 8 + (threadIdx.x >> 5);
    const int lane = threadIdx.x & 31;
    if (n >= NN) return;
    const int s0 = g_off[n];
    const int deg = g_off[n + 1] - s0;
    const int h = lane >> 3;

    const float4* asrc4 = (const float4*)g_asrc1;
    float4 ad4 = *(const float4*)(g_adst1 + n * H1);
    float ad[H1] = {ad4.x, ad4.y, ad4.z, ad4.w};

    // pass 1: online (max, sum)
    float m[H1] = {NEGBIG, NEGBIG, NEGBIG, NEGBIG};
    float sa[H1] = {0.f, 0.f, 0.f, 0.f};
    for (int i = lane; i < deg; i += 32) {
        float4 as = asrc4[g_srcs[s0 + i]];
        float l[H1];
        l[0] = lrelu(as.x + ad[0]);
        l[1] = lrelu(as.y + ad[1]);
        l[2] = lrelu(as.z + ad[2]);
        l[3] = lrelu(as.w + ad[3]);
#pragma unroll
        for (int hh = 0; hh < H1; hh++) {
            float M = fmaxf(m[hh], l[hh]);
            sa[hh] = sa[hh] * expf(m[hh] - M) + expf(l[hh] - M);
            m[hh] = M;
        }
    }
#pragma unroll
    for (int o = 16; o; o >>= 1) {
#pragma unroll
        for (int hh = 0; hh < H1; hh++) {
            float mo = __shfl_xor_sync(0xffffffffu, m[hh], o);
            float so = __shfl_xor_sync(0xffffffffu, sa[hh], o);
            float M = fmaxf(m[hh], mo);
            sa[hh] = sa[hh] * expf(m[hh] - M) + so * expf(mo - M);
            m[hh] = M;
        }
    }
    const float Mh = m[h];
    const float SINV = 1.0f / sa[h];
    const float adh = ad[h];

    // pass 2: aggregate 16 channels per lane, 2-edge unrolled for MLP
    float acc[16];
#pragma unroll
    for (int q = 0; q < 16; q++) acc[q] = 0.f;

    const __half* hb = g_h1h + 16 * lane;
    int i = 0;
    for (; i + 2 <= deg; i += 2) {
        int sA = g_srcs[s0 + i];
        int sB = g_srcs[s0 + i + 1];
        float asA = __ldg(&g_asrc1[sA * H1 + h]);
        float asB = __ldg(&g_asrc1[sB * H1 + h]);
        const uint4* pA = (const uint4*)(hb + (size_t)sA * D1);
        const uint4* pB = (const uint4*)(hb + (size_t)sB * D1);
        uint4 a0 = pA[0], a1 = pA[1];
        uint4 b0 = pB[0], b1 = pB[1];
        float cA = expf(lrelu(asA + adh) - Mh) * SINV;
        float cB = expf(lrelu(asB + adh) - Mh) * SINV;
        const __half2* ca0 = (const __half2*)&a0;
        const __half2* ca1 = (const __half2*)&a1;
        const __half2* cb0 = (const __half2*)&b0;
        const __half2* cb1 = (const __half2*)&b1;
#pragma unroll
        for (int q = 0; q < 4; q++) {
            float2 vA0 = __half22float2(ca0[q]);
            float2 vA1 = __half22float2(ca1[q]);
            float2 vB0 = __half22float2(cb0[q]);
            float2 vB1 = __half22float2(cb1[q]);
            acc[2 * q + 0] = fmaf(cA, vA0.x, acc[2 * q + 0]);
            acc[2 * q + 1] = fmaf(cA, vA0.y, acc[2 * q + 1]);
            acc[8 + 2 * q + 0] = fmaf(cA, vA1.x, acc[8 + 2 * q + 0]);
            acc[8 + 2 * q + 1] = fmaf(cA, vA1.y, acc[8 + 2 * q + 1]);
            acc[2 * q + 0] = fmaf(cB, vB0.x, acc[2 * q + 0]);
            acc[2 * q + 1] = fmaf(cB, vB0.y, acc[2 * q + 1]);
            acc[8 + 2 * q + 0] = fmaf(cB, vB1.x, acc[8 + 2 * q + 0]);
            acc[8 + 2 * q + 1] = fmaf(cB, vB1.y, acc[8 + 2 * q + 1]);
        }
    }
    if (i < deg) {
        int s = g_srcs[s0 + i];
        float asv = __ldg(&g_asrc1[s * H1 + h]);
        float coef = expf(lrelu(asv + adh) - Mh) * SINV;
        const uint4* p = (const uint4*)(hb + (size_t)s * D1);
        uint4 u0 = p[0], u1 = p[1];
        const __half2* c0 = (const __half2*)&u0;
        const __half2* c1 = (const __half2*)&u1;
#pragma unroll
        for (int q = 0; q < 4; q++) {
            float2 v0 = __half22float2(c0[q]);
            float2 v1 = __half22float2(c1[q]);
            acc[2 * q + 0] = fmaf(coef, v0.x, acc[2 * q + 0]);
            acc[2 * q + 1] = fmaf(coef, v0.y, acc[2 * q + 1]);
            acc[8 + 2 * q + 0] = fmaf(coef, v1.x, acc[8 + 2 * q + 0]);
            acc[8 + 2 * q + 1] = fmaf(coef, v1.y, acc[8 + 2 * q + 1]);
        }
    }

    // bias + ELU
    float* orow = g_out1 + (size_t)n * D1 + 16 * lane;
    const float* bp = b1 + 16 * lane;
#pragma unroll
    for (int q4 = 0; q4 < 4; q4++) {
        float4 bb = *(const float4*)(bp + 4 * q4);
        float4 o;
        o.x = acc[4 * q4 + 0] + bb.x; o.x = o.x > 0.f ? o.x : expm1f(o.x);
        o.y = acc[4 * q4 + 1] + bb.y; o.y = o.y > 0.f ? o.y : expm1f(o.y);
        o.z = acc[4 * q4 + 2] + bb.z; o.z = o.z > 0.f ? o.z : expm1f(o.z);
        o.w = acc[4 * q4 + 3] + bb.w; o.w = o.w > 0.f ? o.w : expm1f(o.w);
        *(float4*)(orow + 4 * q4) = o;
    }
}

// ==================== Layer 2 ====================
__global__ __launch_bounds__(256) void gemm2_kernel(const float* __restrict__ W2) {
    __shared__ float w[D1 * CLS];
    int t = threadIdx.x;
    for (int i = t; i < D1 * CLS; i += 256) w[i] = W2[i];
    __syncthreads();
    int warp = blockIdx.x * 8 + (t >> 5);
    int lane = t & 31;
    if (warp >= NN) return;
    const float* row = g_out1 + (size_t)warp * D1;
    float acc[CLS] = {0.f, 0.f, 0.f, 0.f, 0.f, 0.f};
    for (int k = lane; k < D1; k += 32) {
        float v = row[k];
        const float* wr = &w[k * CLS];
#pragma unroll
        for (int c = 0; c < CLS; c++) acc[c] = fmaf(v, wr[c], acc[c]);
    }
#pragma unroll
    for (int o = 16; o; o >>= 1)
#pragma unroll
        for (int c = 0; c < CLS; c++) acc[c] += __shfl_xor_sync(0xffffffffu, acc[c], o);
    if (lane == 0) {
#pragma unroll
        for (int c = 0; c < CLS; c++) g_h2[warp * CLS + c] = acc[c];
    }
}

__global__ void alpha2_kernel(const float* __restrict__ a_s, const float* __restrict__ a_d) {
    int n = blockIdx.x * blockDim.x + threadIdx.x;
    if (n >= NN) return;
    float s = 0.f, d = 0.f;
#pragma unroll
    for (int c = 0; c < CLS; c++) {
        float v = g_h2[n * CLS + c];
        s = fmaf(v, a_s[c], s);
        d = fmaf(v, a_d[c], d);
    }
    g_as2[n] = s;
    g_ad2[n] = d;
}

__global__ __launch_bounds__(128) void agg2_kernel(const float* __restrict__ b2,
                                                   float* __restrict__ out) {
    int n = blockIdx.x * 4 + (threadIdx.x >> 5);
    int lane = threadIdx.x & 31;
    if (n >= NN) return;
    int s0 = g_off[n];
    int deg = g_off[n + 1] - s0;
    float ad = g_ad2[n];

    float lmax = -INFINITY;
    for (int i = lane; i < deg; i += 32) {
        int s = g_srcs[s0 + i];
        lmax = fmaxf(lmax, lrelu(g_as2[s] + ad));
    }
#pragma unroll
    for (int o = 16; o; o >>= 1) lmax = fmaxf(lmax, __shfl_xor_sync(0xffffffffu, lmax, o));

    float lsum = 0.f;
    for (int i = lane; i < deg; i += 32) {
        int s = g_srcs[s0 + i];
        lsum += expf(lrelu(g_as2[s] + ad) - lmax);
    }
#pragma unroll
    for (int o = 16; o; o >>= 1) lsum += __shfl_xor_sync(0xffffffffu, lsum, o);
    float inv = 1.0f / lsum;

    float acc[CLS] = {0.f, 0.f, 0.f, 0.f, 0.f, 0.f};
    for (int i = lane; i < deg; i += 32) {
        int s = g_srcs[s0 + i];
        float coef = expf(lrelu(g_as2[s] + ad) - lmax) * inv;
        const float* hp = g_h2 + s * CLS;
#pragma unroll
        for (int c = 0; c < CLS; c++) acc[c] = fmaf(coef, hp[c], acc[c]);
    }
#pragma unroll
    for (int o = 16; o; o >>= 1)
#pragma unroll
        for (int c = 0; c < CLS; c++) acc[c] += __shfl_xor_sync(0xffffffffu, acc[c], o);

    if (lane == 0) {
#pragma unroll
        for (int c = 0; c < CLS; c++) out[n * CLS + c] = acc[c] + b2[c];
    }
}

// ==================== Launch ====================
extern "C" void kernel_launch(void* const* d_in, const int* in_sizes, int n_in,
                              void* d_out, int out_size) {
    const float* x   = (const float*)d_in[0];
    const int*   ei  = (const int*)  d_in[1];
    const float* W1  = (const float*)d_in[2];
    const float* as1 = (const float*)d_in[3];
    const float* ad1 = (const float*)d_in[4];
    const float* b1  = (const float*)d_in[5];
    const float* W2  = (const float*)d_in[6];
    const float* as2 = (const float*)d_in[7];
    const float* ad2 = (const float*)d_in[8];
    const float* b2  = (const float*)d_in[9];
    float* out = (float*)d_out;

    static cudaStream_t s2 = nullptr;
    static cudaEvent_t evFork = nullptr, evJoin = nullptr;
    if (!s2) {
        cudaFuncSetAttribute(mma1_kernel, cudaFuncAttributeMaxDynamicSharedMemorySize, SMEM_SZ);
        cudaStreamCreateWithFlags(&s2, cudaStreamNonBlocking);
        cudaEventCreateWithFlags(&evFork, cudaEventDisableTiming);
        cudaEventCreateWithFlags(&evJoin, cudaEventDisableTiming);
    }

    // Fork: CSR build on s2, concurrent with convw1+mma1 on main stream.
    cudaEventRecord(evFork, 0);
    cudaStreamWaitEvent(s2, evFork, 0);

    zero_deg_kernel<<<(NN + 255) / 256, 256, 0, s2>>>();
    count_kernel<<<(ETOT + 255) / 256, 256, 0, s2>>>(ei);
    scan_kernel<<<1, 1024, 0, s2>>>();
    scatter_kernel<<<(ETOT + 255) / 256, 256, 0, s2>>>(ei);
    cudaEventRecord(evJoin, s2);

    // Main stream: W1 convert -> GEMM (+fused alpha1)
    convw1_kernel<<<dim3(D1 / 32, FIN / 32), 256>>>(W1);
    mma1_kernel<<<dim3(D1 / 256, (NN + 127) / 128), 256, SMEM_SZ>>>(x, as1, ad1);

    // Join: agg1 needs CSR + h1 + alphas
    cudaStreamWaitEvent(0, evJoin, 0);
    agg1_kernel<<<(NN + 7) / 8, 256>>>(b1);

    // Layer 2
    gemm2_kernel<<<(NN + 7) / 8, 256>>>(W2);
    alpha2_kernel<<<(NN + 255) / 256, 256>>>(as2, ad2);
    agg2_kernel<<<(NN + 3) / 4, 128>>>(b2, out);
}

// round 14
// speedup vs baseline: 1.1658x; 1.0066x over previous
#include <cuda_runtime.h>
#include <cuda_fp16.h>
#include <math.h>
#include <stdint.h>

// ---------------- Problem constants ----------------
#define NN    30000
#define EE    480000
#define ETOT  (EE + NN)
#define FIN   4096
#define D1    512
#define H1    4
#define C1    128
#define CLS   6
#define SLOPE 0.2f
#define NEGBIG (-3.402823466e38f)

// ---------------- Device scratch ----------------
__device__ __half g_h1h[(size_t)NN * D1];    // layer-1 linear output, fp16
__device__ __half g_out1h[(size_t)NN * D1];  // post-attention + ELU, fp16
__device__ float g_asrc1[NN * H1];
__device__ float g_adst1[NN * H1];
__device__ float g_h2[NN * CLS];
__device__ float g_as2[NN];
__device__ float g_ad2[NN];
__device__ int   g_deg[NN];
__device__ int   g_off[NN + 1];
__device__ int   g_cur[NN];
__device__ int   g_srcs[ETOT];

// fp16 W1 transposed: [N=512][K=4096]
__device__ __half g_w1t[(size_t)D1 * FIN];

__device__ __forceinline__ float lrelu(float v) { return v > 0.0f ? v : SLOPE * v; }

// ==================== helpers ====================
__device__ __forceinline__ uint32_t smem_u32(const void* p) {
    uint32_t a;
    asm("{ .reg .u64 t; cvta.to.shared.u64 t, %1; cvt.u32.u64 %0, t; }" : "=r"(a) : "l"(p));
    return a;
}

__device__ __forceinline__ void cpa16(uint32_t dst, const void* src) {
    asm volatile("cp.async.cg.shared.global [%0], [%1], 16;\n"
                 :: "r"(dst), "l"(src) : "memory");
}

__device__ __forceinline__ void ldm_x4(uint32_t addr, uint32_t& r0, uint32_t& r1,
                                       uint32_t& r2, uint32_t& r3) {
    asm volatile("ldmatrix.sync.aligned.m8n8.x4.shared.b16 {%0,%1,%2,%3}, [%4];"
                 : "=r"(r0), "=r"(r1), "=r"(r2), "=r"(r3) : "r"(addr));
}

__device__ __forceinline__ void mma_f16(float& d0, float& d1, float& d2, float& d3,
                                        uint32_t a0, uint32_t a1, uint32_t a2, uint32_t a3,
                                        uint32_t b0, uint32_t b1) {
    asm volatile("mma.sync.aligned.m16n8k16.row.col.f32.f16.f16.f32 "
                 "{%0,%1,%2,%3}, {%4,%5,%6,%7}, {%8,%9}, {%0,%1,%2,%3};"
                 : "+f"(d0), "+f"(d1), "+f"(d2), "+f"(d3)
                 : "r"(a0), "r"(a1), "r"(a2), "r"(a3), "r"(b0), "r"(b1));
}

__device__ __forceinline__ uint32_t pack_h2(float a, float b) {
    __half2 h = __halves2half2(__float2half_rn(a), __float2half_rn(b));
    return *(uint32_t*)&h;
}

// ==================== W1 -> fp16 transposed (32x32 tile) ====================
__global__ __launch_bounds__(256) void convw1_kernel(const float* __restrict__ W1) {
    __shared__ float tile[32][33];
    const int kb = blockIdx.y * 32;
    const int nb = blockIdx.x * 32;
    const int t = threadIdx.x;
    const int r = t >> 5, c = t & 31;
#pragma unroll
    for (int rr = r; rr < 32; rr += 8)
        tile[rr][c] = W1[(size_t)(kb + rr) * D1 + nb + c];
    __syncthreads();
#pragma unroll
    for (int rr = r; rr < 32; rr += 8) {
        float v = tile[c][rr];
        g_w1t[(size_t)(nb + rr) * FIN + kb + c] = __float2half_rn(v);
    }
}

// ==================== GEMM1 + fused alpha1: fp16 mma.sync, 128x256 tile ====================
#define BK       32
#define CHUNKS   (FIN / BK)      // 128
#define TILE_A_B (128 * 80)      // 10240
#define TILE_B_B (256 * 80)      // 20480
#define OFF_A    0
#define OFF_B    (TILE_A_B)
#define STAGE_B  (TILE_A_B + TILE_B_B)   // 30720
#define SMEM_SZ  (2 * STAGE_B)           // 61440

__global__ __launch_bounds__(256) void mma1_kernel(const float* __restrict__ x,
                                                   const float* __restrict__ a_s,
                                                   const float* __restrict__ a_d) {
    extern __shared__ __align__(16) char dsm[];
    const uint32_t sb = smem_u32(dsm);
    __shared__ float s_as[256];
    __shared__ float s_ad[256];

    const int tid = threadIdx.x;
    const int wid = tid >> 5;
    const int lane = tid & 31;
    const int warp_m = wid >> 2;
    const int warp_n = wid & 3;
    const int block_row = blockIdx.y * 128;
    const int nbase = blockIdx.x * 256;

    s_as[tid] = a_s[nbase + tid];
    s_ad[tid] = a_d[nbase + tid];

    const int a_r = tid >> 1;
    const int a_half = tid & 1;
    const bool a_ok = (block_row + a_r) < NN;
    const float* a_src = x + (size_t)(block_row + a_r) * FIN + a_half * 16;
    const uint32_t a_dso = (uint32_t)(a_r * 80 + a_half * 32);

    float4 xr[4];
    auto ldA = [&](int c) {
        if (a_ok) {
            const float4* p = (const float4*)(a_src + c * BK);
#pragma unroll
            for (int q = 0; q < 4; q++) xr[q] = p[q];
        } else {
            float4 z = make_float4(0.f, 0.f, 0.f, 0.f);
#pragma unroll
            for (int q = 0; q < 4; q++) xr[q] = z;
        }
    };
    auto stsA = [&](int s) {
        const uint32_t base = sb + s * STAGE_B;
        uint4 h0, h1;
        h0.x = pack_h2(xr[0].x, xr[0].y); h0.y = pack_h2(xr[0].z, xr[0].w);
        h0.z = pack_h2(xr[1].x, xr[1].y); h0.w = pack_h2(xr[1].z, xr[1].w);
        h1.x = pack_h2(xr[2].x, xr[2].y); h1.y = pack_h2(xr[2].z, xr[2].w);
        h1.z = pack_h2(xr[3].x, xr[3].y); h1.w = pack_h2(xr[3].z, xr[3].w);
        uint32_t ah = base + OFF_A + a_dso;
        asm volatile("st.shared.v4.b32 [%0], {%1,%2,%3,%4};" :: "r"(ah), "r"(h0.x), "r"(h0.y), "r"(h0.z), "r"(h0.w));
        asm volatile("st.shared.v4.b32 [%0], {%1,%2,%3,%4};" :: "r"(ah + 16), "r"(h1.x), "r"(h1.y), "r"(h1.z), "r"(h1.w));
    };

    auto cpB = [&](int c, int s) {
        const uint32_t base = sb + s * STAGE_B;
        const int kbase = c * BK;
#pragma unroll
        for (int i = tid; i < 1024; i += 256) {
            int r = i >> 2, q = i & 3;
            uint32_t dso = (uint32_t)(r * 80 + q * 16);
            size_t se = (size_t)(nbase + r) * FIN + kbase + q * 8;
            cpa16(base + OFF_B + dso, g_w1t + se);
        }
    };

    const uint32_t a_off = (uint32_t)((warp_m * 64 + (lane & 15)) * 80 + (lane >> 4) * 16);
    const uint32_t b_off = (uint32_t)((warp_n * 64 + (lane & 7) + ((lane >> 4) << 3)) * 80 +
                                      ((lane >> 3) & 1) * 16);

    float acc[4][8][4];
#pragma unroll
    for (int i = 0; i < 4; i++)
#pragma unroll
        for (int j = 0; j < 8; j++)
#pragma unroll
            for (int q = 0; q < 4; q++) acc[i][j][q] = 0.0f;

    ldA(0);
    stsA(0);
    cpB(0, 0);
    asm volatile("cp.async.commit_group;\n" ::: "memory");
    ldA(1);

    for (int c = 0; c < CHUNKS; c++) {
        const int s = c & 1;
        asm volatile("cp.async.wait_group 0;\n" ::: "memory");
        __syncthreads();

        if (c + 1 < CHUNKS) {
            stsA(s ^ 1);
            cpB(c + 1, s ^ 1);
            asm volatile("cp.async.commit_group;\n" ::: "memory");
        }
        if (c + 2 < CHUNKS) ldA(c + 2);

        const uint32_t stg = sb + s * STAGE_B;
        const uint32_t a_base = stg + OFF_A + a_off;
        const uint32_t b_base = stg + OFF_B + b_off;

#pragma unroll
        for (int kk = 0; kk < 2; kk++) {
            uint32_t av[4][4];
#pragma unroll
            for (int i = 0; i < 4; i++) {
                uint32_t ao = (uint32_t)(i * 16 * 80 + kk * 32);
                ldm_x4(a_base + ao, av[i][0], av[i][1], av[i][2], av[i][3]);
            }
#pragma unroll
            for (int j2 = 0; j2 < 4; j2++) {
                uint32_t b0, b1, b2, b3;
                uint32_t bo = (uint32_t)(j2 * 16 * 80 + kk * 32);
                ldm_x4(b_base + bo, b0, b1, b2, b3);
#pragma unroll
                for (int i = 0; i < 4; i++) {
                    float* d0 = acc[i][2 * j2];
                    float* d1 = acc[i][2 * j2 + 1];
                    mma_f16(d0[0], d0[1], d0[2], d0[3],
                            av[i][0], av[i][1], av[i][2], av[i][3], b0, b1);
                    mma_f16(d1[0], d1[1], d1[2], d1[3],
                            av[i][0], av[i][1], av[i][2], av[i][3], b2, b3);
                }
            }
        }
    }

    __syncthreads();
    float* psred = (float*)dsm;
    float* pdred = psred + 512;

#pragma unroll
    for (int i = 0; i < 4; i++) {
        int row0 = block_row + warp_m * 64 + i * 16 + (lane >> 2);
        float ps0 = 0.f, pd0 = 0.f, ps1 = 0.f, pd1 = 0.f;
#pragma unroll
        for (int j = 0; j < 8; j++) {
            int cl = warp_n * 64 + j * 8 + (lane & 3) * 2;
            int col = nbase + cl;
            if (row0 < NN)
                *(uint32_t*)(g_h1h + (size_t)row0 * D1 + col) = pack_h2(acc[i][j][0], acc[i][j][1]);
            if (row0 + 8 < NN)
                *(uint32_t*)(g_h1h + (size_t)(row0 + 8) * D1 + col) = pack_h2(acc[i][j][2], acc[i][j][3]);
            float as0 = s_as[cl], as1 = s_as[cl + 1];
            float ad0 = s_ad[cl], ad1 = s_ad[cl + 1];
            ps0 = fmaf(acc[i][j][0], as0, ps0); ps0 = fmaf(acc[i][j][1], as1, ps0);
            pd0 = fmaf(acc[i][j][0], ad0, pd0); pd0 = fmaf(acc[i][j][1], ad1, pd0);
            ps1 = fmaf(acc[i][j][2], as0, ps1); ps1 = fmaf(acc[i][j][3], as1, ps1);
            pd1 = fmaf(acc[i][j][2], ad0, pd1); pd1 = fmaf(acc[i][j][3], ad1, pd1);
        }
#pragma unroll
        for (int o = 1; o <= 2; o <<= 1) {
            ps0 += __shfl_xor_sync(0xffffffffu, ps0, o);
            pd0 += __shfl_xor_sync(0xffffffffu, pd0, o);
            ps1 += __shfl_xor_sync(0xffffffffu, ps1, o);
            pd1 += __shfl_xor_sync(0xffffffffu, pd1, o);
        }
        if ((lane & 3) == 0) {
            int r64 = i * 16 + (lane >> 2);
            int bidx = (warp_m * 4 + warp_n) * 64;
            psred[bidx + r64] = ps0;
            pdred[bidx + r64] = pd0;
            psred[bidx + r64 + 8] = ps1;
            pdred[bidx + r64 + 8] = pd1;
        }
    }
    __syncthreads();

    {
        int wm = tid >> 7;
        int hl = (tid >> 6) & 1;
        int r = tid & 63;
        int row = block_row + wm * 64 + r;
        if (row < NN) {
            int b0 = (wm * 4 + 2 * hl) * 64 + r;
            int b1 = (wm * 4 + 2 * hl + 1) * 64 + r;
            int head = (nbase >> 7) + hl;
            g_asrc1[row * H1 + head] = psred[b0] + psred[b1];
            g_adst1[row * H1 + head] = pdred[b0] + pdred[b1];
        }
    }
}

// ==================== CSR build ====================
__global__ void zero_deg_kernel() {
    int i = blockIdx.x * blockDim.x + threadIdx.x;
    if (i < NN) g_deg[i] = 0;
}

__global__ void count_kernel(const int* __restrict__ ei) {
    int e = blockIdx.x * blockDim.x + threadIdx.x;
    if (e >= ETOT) return;
    int dst = (e < EE) ? ei[EE + e] : (e - EE);
    atomicAdd(&g_deg[dst], 1);
}

__global__ __launch_bounds__(1024) void scan_kernel() {
    __shared__ int part[1024];
    const int t = threadIdx.x;
    const int CH = (NN + 1023) / 1024;
    const int base = t * CH;
    int s = 0;
    for (int i = 0; i < CH; i++) {
        int idx = base + i;
        if (idx < NN) s += g_deg[idx];
    }
    part[t] = s;
    __syncthreads();
    for (int o = 1; o < 1024; o <<= 1) {
        int v = (t >= o) ? part[t - o] : 0;
        __syncthreads();
        part[t] += v;
        __syncthreads();
    }
    int run = part[t] - s;
    for (int i = 0; i < CH; i++) {
        int idx = base + i;
        if (idx < NN) {
            g_off[idx] = run;
            g_cur[idx] = run;
            run += g_deg[idx];
        }
    }
    if (t == 1023) g_off[NN] = part[1023];
}

__global__ void scatter_kernel(const int* __restrict__ ei) {
    int e = blockIdx.x * blockDim.x + threadIdx.x;
    if (e >= ETOT) return;
    int src, dst;
    if (e < EE) { src = ei[e]; dst = ei[EE + e]; }
    else        { src = e - EE; dst = e - EE; }
    int pos = atomicAdd(&g_cur[dst], 1);
    g_srcs[pos] = src;
}

// ==================== Layer 1: warp-per-node softmax + aggregate + ELU (fp16 out) ====================
__global__ __launch_bounds__(256) void agg1_kernel(const float* __restrict__ b1) {
    const int n = blockIdx.x * 8 + (threadIdx.x >> 5);
    const int lane = threadIdx.x & 31;
    if (n >= NN) return;
    const int s0 = g_off[n];
    const int deg = g_off[n + 1] - s0;
    const int h = lane >> 3;

    const float4* asrc4 = (const float4*)g_asrc1;
    float4 ad4 = *(const float4*)(g_adst1 + n * H1);
    float ad[H1] = {ad4.x, ad4.y, ad4.z, ad4.w};

    float m[H1] = {NEGBIG, NEGBIG, NEGBIG, NEGBIG};
    float sa[H1] = {0.f, 0.f, 0.f, 0.f};
    for (int i = lane; i < deg; i += 32) {
        float4 as = asrc4[g_srcs[s0 + i]];
        float l[H1];
        l[0] = lrelu(as.x + ad[0]);
        l[1] = lrelu(as.y + ad[1]);
        l[2] = lrelu(as.z + ad[2]);
        l[3] = lrelu(as.w + ad[3]);
#pragma unroll
        for (int hh = 0; hh < H1; hh++) {
            float M = fmaxf(m[hh], l[hh]);
            sa[hh] = sa[hh] * expf(m[hh] - M) + expf(l[hh] - M);
            m[hh] = M;
        }
    }
#pragma unroll
    for (int o = 16; o; o >>= 1) {
#pragma unroll
        for (int hh = 0; hh < H1; hh++) {
            float mo = __shfl_xor_sync(0xffffffffu, m[hh], o);
            float so = __shfl_xor_sync(0xffffffffu, sa[hh], o);
            float M = fmaxf(m[hh], mo);
            sa[hh] = sa[hh] * expf(m[hh] - M) + so * expf(mo - M);
            m[hh] = M;
        }
    }
    const float Mh = m[h];
    const float SINV = 1.0f / sa[h];
    const float adh = ad[h];

    float acc[16];
#pragma unroll
    for (int q = 0; q < 16; q++) acc[q] = 0.f;

    const __half* hb = g_h1h + 16 * lane;
    int i = 0;
    for (; i + 2 <= deg; i += 2) {
        int sA = g_srcs[s0 + i];
        int sB = g_srcs[s0 + i + 1];
        float asA = __ldg(&g_asrc1[sA * H1 + h]);
        float asB = __ldg(&g_asrc1[sB * H1 + h]);
        const uint4* pA = (const uint4*)(hb + (size_t)sA * D1);
        const uint4* pB = (const uint4*)(hb + (size_t)sB * D1);
        uint4 a0 = pA[0], a1 = pA[1];
        uint4 b0 = pB[0], b1 = pB[1];
        float cA = expf(lrelu(asA + adh) - Mh) * SINV;
        float cB = expf(lrelu(asB + adh) - Mh) * SINV;
        const __half2* ca0 = (const __half2*)&a0;
        const __half2* ca1 = (const __half2*)&a1;
        const __half2* cb0 = (const __half2*)&b0;
        const __half2* cb1 = (const __half2*)&b1;
#pragma unroll
        for (int q = 0; q < 4; q++) {
            float2 vA0 = __half22float2(ca0[q]);
            float2 vA1 = __half22float2(ca1[q]);
            float2 vB0 = __half22float2(cb0[q]);
            float2 vB1 = __half22float2(cb1[q]);
            acc[2 * q + 0] = fmaf(cA, vA0.x, acc[2 * q + 0]);
            acc[2 * q + 1] = fmaf(cA, vA0.y, acc[2 * q + 1]);
            acc[8 + 2 * q + 0] = fmaf(cA, vA1.x, acc[8 + 2 * q + 0]);
            acc[8 + 2 * q + 1] = fmaf(cA, vA1.y, acc[8 + 2 * q + 1]);
            acc[2 * q + 0] = fmaf(cB, vB0.x, acc[2 * q + 0]);
            acc[2 * q + 1] = fmaf(cB, vB0.y, acc[2 * q + 1]);
            acc[8 + 2 * q + 0] = fmaf(cB, vB1.x, acc[8 + 2 * q + 0]);
            acc[8 + 2 * q + 1] = fmaf(cB, vB1.y, acc[8 + 2 * q + 1]);
        }
    }
    if (i < deg) {
        int s = g_srcs[s0 + i];
        float asv = __ldg(&g_asrc1[s * H1 + h]);
        float coef = expf(lrelu(asv + adh) - Mh) * SINV;
        const uint4* p = (const uint4*)(hb + (size_t)s * D1);
        uint4 u0 = p[0], u1 = p[1];
        const __half2* c0 = (const __half2*)&u0;
        const __half2* c1 = (const __half2*)&u1;
#pragma unroll
        for (int q = 0; q < 4; q++) {
            float2 v0 = __half22float2(c0[q]);
            float2 v1 = __half22float2(c1[q]);
            acc[2 * q + 0] = fmaf(coef, v0.x, acc[2 * q + 0]);
            acc[2 * q + 1] = fmaf(coef, v0.y, acc[2 * q + 1]);
            acc[8 + 2 * q + 0] = fmaf(coef, v1.x, acc[8 + 2 * q + 0]);
            acc[8 + 2 * q + 1] = fmaf(coef, v1.y, acc[8 + 2 * q + 1]);
        }
    }

    // bias + ELU -> fp16 out1 (16 halves = 1 uint4 store)
    const float* bp = b1 + 16 * lane;
    uint4 ov;
    uint32_t* op = (uint32_t*)&ov;
#pragma unroll
    for (int q4 = 0; q4 < 4; q4++) {
        float4 bb = *(const float4*)(bp + 4 * q4);
        float e0 = acc[4 * q4 + 0] + bb.x; e0 = e0 > 0.f ? e0 : expm1f(e0);
        float e1 = acc[4 * q4 + 1] + bb.y; e1 = e1 > 0.f ? e1 : expm1f(e1);
        float e2 = acc[4 * q4 + 2] + bb.z; e2 = e2 > 0.f ? e2 : expm1f(e2);
        float e3 = acc[4 * q4 + 3] + bb.w; e3 = e3 > 0.f ? e3 : expm1f(e3);
        op[q4] = 0;
        op[q4] = pack_h2(e0, e1) | 0;  // low half2
        // pack both half2s into consecutive 32-bit words
        uint32_t hi = pack_h2(e2, e3);
        // store as two words: q4 handles 4 halves -> op uses 2 words per q4? No:
        // 16 halves = 8 x half2 = 8 words, but uint4 = 4 words. Use two uint4 stores.
        (void)hi;
    }
    // simpler: two uint4 stores of 8 halves each
    {
        __half* orow = g_out1h + (size_t)n * D1 + 16 * lane;
        uint4 w0, w1;
        uint32_t* p0 = (uint32_t*)&w0;
        uint32_t* p1 = (uint32_t*)&w1;
#pragma unroll
        for (int q = 0; q < 4; q++) {
            float4 bb = *(const float4*)(bp + 4 * q);
            float e0 = acc[4 * q + 0] + bb.x; e0 = e0 > 0.f ? e0 : expm1f(e0);
            float e1 = acc[4 * q + 1] + bb.y; e1 = e1 > 0.f ? e1 : expm1f(e1);
            float e2 = acc[4 * q + 2] + bb.z; e2 = e2 > 0.f ? e2 : expm1f(e2);
            float e3 = acc[4 * q + 3] + bb.w; e3 = e3 > 0.f ? e3 : expm1f(e3);
            if (q < 2) {
                p0[2 * q + 0] = pack_h2(e0, e1);
                p0[2 * q + 1] = pack_h2(e2, e3);
            } else {
                p1[2 * (q - 2) + 0] = pack_h2(e0, e1);
                p1[2 * (q - 2) + 1] = pack_h2(e2, e3);
            }
        }
        *(uint4*)(orow) = w0;
        *(uint4*)(orow + 8) = w1;
    }
}

// ==================== Layer 2: gemm2 (fp16 in) + fused alpha2 ====================
__global__ __launch_bounds__(256) void gemm2_kernel(const float* __restrict__ W2,
                                                    const float* __restrict__ a_s,
                                                    const float* __restrict__ a_d) {
    __shared__ float w[D1 * CLS];
    int t = threadIdx.x;
    for (int i = t; i < D1 * CLS; i += 256) w[i] = W2[i];
    __syncthreads();
    int warp = blockIdx.x * 8 + (t >> 5);
    int lane = t & 31;
    if (warp >= NN) return;
    const __half2* row2 = (const __half2*)(g_out1h + (size_t)warp * D1);
    float acc[CLS] = {0.f, 0.f, 0.f, 0.f, 0.f, 0.f};
    for (int p = lane; p < D1 / 2; p += 32) {
        float2 v = __half22float2(row2[p]);
        const float* wr0 = &w[(2 * p) * CLS];
        const float* wr1 = &w[(2 * p + 1) * CLS];
#pragma unroll
        for (int c = 0; c < CLS; c++) {
            acc[c] = fmaf(v.x, wr0[c], acc[c]);
            acc[c] = fmaf(v.y, wr1[c], acc[c]);
        }
    }
#pragma unroll
    for (int o = 16; o; o >>= 1)
#pragma unroll
        for (int c = 0; c < CLS; c++) acc[c] += __shfl_xor_sync(0xffffffffu, acc[c], o);
    if (lane == 0) {
        float s2 = 0.f, d2 = 0.f;
#pragma unroll
        for (int c = 0; c < CLS; c++) {
            g_h2[warp * CLS + c] = acc[c];
            s2 = fmaf(acc[c], a_s[c], s2);
            d2 = fmaf(acc[c], a_d[c], d2);
        }
        g_as2[warp] = s2;
        g_ad2[warp] = d2;
    }
}

// ==================== Layer 2 aggregation ====================
__global__ __launch_bounds__(128) void agg2_kernel(const float* __restrict__ b2,
                                                   float* __restrict__ out) {
    int n = blockIdx.x * 4 + (threadIdx.x >> 5);
    int lane = threadIdx.x & 31;
    if (n >= NN) return;
    int s0 = g_off[n];
    int deg = g_off[n + 1] - s0;
    float ad = g_ad2[n];

    float lmax = -INFINITY;
    for (int i = lane; i < deg; i += 32) {
        int s = g_srcs[s0 + i];
        lmax = fmaxf(lmax, lrelu(g_as2[s] + ad));
    }
#pragma unroll
    for (int o = 16; o; o >>= 1) lmax = fmaxf(lmax, __shfl_xor_sync(0xffffffffu, lmax, o));

    float lsum = 0.f;
    for (int i = lane; i < deg; i += 32) {
        int s = g_srcs[s0 + i];
        lsum += expf(lrelu(g_as2[s] + ad) - lmax);
    }
#pragma unroll
    for (int o = 16; o; o >>= 1) lsum += __shfl_xor_sync(0xffffffffu, lsum, o);
    float inv = 1.0f / lsum;

    float acc[CLS] = {0.f, 0.f, 0.f, 0.f, 0.f, 0.f};
    for (int i = lane; i < deg; i += 32) {
        int s = g_srcs[s0 + i];
        float coef = expf(lrelu(g_as2[s] + ad) - lmax) * inv;
        const float* hp = g_h2 + s * CLS;
#pragma unroll
        for (int c = 0; c < CLS; c++) acc[c] = fmaf(coef, hp[c], acc[c]);
    }
#pragma unroll
    for (int o = 16; o; o >>= 1)
#pragma unroll
        for (int c = 0; c < CLS; c++) acc[c] += __shfl_xor_sync(0xffffffffu, acc[c], o);

    if (lane == 0) {
#pragma unroll
        for (int c = 0; c < CLS; c++) out[n * CLS + c] = acc[c] + b2[c];
    }
}

// ==================== Launch ====================
extern "C" void kernel_launch(void* const* d_in, const int* in_sizes, int n_in,
                              void* d_out, int out_size) {
    const float* x   = (const float*)d_in[0];
    const int*   ei  = (const int*)  d_in[1];
    const float* W1  = (const float*)d_in[2];
    const float* as1 = (const float*)d_in[3];
    const float* ad1 = (const float*)d_in[4];
    const float* b1  = (const float*)d_in[5];
    const float* W2  = (const float*)d_in[6];
    const float* as2 = (const float*)d_in[7];
    const float* ad2 = (const float*)d_in[8];
    const float* b2  = (const float*)d_in[9];
    float* out = (float*)d_out;

    static cudaStream_t s2 = nullptr;
    static cudaEvent_t evFork = nullptr, evJoin = nullptr;
    if (!s2) {
        cudaFuncSetAttribute(mma1_kernel, cudaFuncAttributeMaxDynamicSharedMemorySize, SMEM_SZ);
        cudaStreamCreateWithFlags(&s2, cudaStreamNonBlocking);
        cudaEventCreateWithFlags(&evFork, cudaEventDisableTiming);
        cudaEventCreateWithFlags(&evJoin, cudaEventDisableTiming);
    }

    // Fork: CSR build on s2, concurrent with convw1+mma1 on main stream.
    cudaEventRecord(evFork, 0);
    cudaStreamWaitEvent(s2, evFork, 0);

    zero_deg_kernel<<<(NN + 255) / 256, 256, 0, s2>>>();
    count_kernel<<<(ETOT + 255) / 256, 256, 0, s2>>>(ei);
    scan_kernel<<<1, 1024, 0, s2>>>();
    scatter_kernel<<<(ETOT + 255) / 256, 256, 0, s2>>>(ei);
    cudaEventRecord(evJoin, s2);

    // Main stream: W1 convert -> GEMM (+fused alpha1)
    convw1_kernel<<<dim3(D1 / 32, FIN / 32), 256>>>(W1);
    mma1_kernel<<<dim3(D1 / 256, (NN + 127) / 128), 256, SMEM_SZ>>>(x, as1, ad1);

    // Join: agg1 needs CSR + h1 + alphas
    cudaStreamWaitEvent(0, evJoin, 0);
    agg1_kernel<<<(NN + 7) / 8, 256>>>(b1);

    // Layer 2 (gemm2 + alpha2 fused), then aggregation
    gemm2_kernel<<<(NN + 7) / 8, 256>>>(W2, as2, ad2);
    agg2_kernel<<<(NN + 3) / 4, 128>>>(b2, out);
}